// round 1
// baseline (speedup 1.0000x reference)
#include <cuda_runtime.h>
#include <math.h>

#define NB   8
#define LSEQ 4096
#define HIN  1024
#define HD   1024
#define MTOT (NB * LSEQ)   // 32768

// Scratch: per-(m, h) scan coefficients (128 MB each). Static device arrays —
// no runtime allocation (harness rule).
__device__ float g_a[(size_t)MTOT * HD];   // log_coeffs
__device__ float g_b[(size_t)MTOT * HD];   // log_z + log_g(h_inter)

__device__ __forceinline__ float softplusf(float v) {
    // stable: for large v, softplus(v) ~ v; exp underflow handled by log1pf(0)=0
    return v > 20.f ? v : log1pf(__expf(v));
}

// ---------------------------------------------------------------------------
// Kernel 1: fused SGEMM + log-space activation epilogue.
// Block tile: 128 rows (m) x 64 channels (h). For each channel we need TWO
// dot products: W[h] (-> z) and W[H + h] (-> h_inter). Both W tiles are staged
// into the same 128-wide Bs tile (cols 0..63 = z-rows, 64..127 = hi-rows).
// Per thread: 8 rows x 4 channels x 2 accumulators = 64 FMAs per k-step.
// ---------------------------------------------------------------------------
__global__ __launch_bounds__(256) void gemm_act_kernel(
    const float* __restrict__ x,     // (MTOT, HIN)
    const float* __restrict__ W,     // (2*HD, HIN)
    const float* __restrict__ bias)  // (2*HD)
{
    __shared__ float As[16 * 128];   // [k][m]
    __shared__ float Bs[16 * 128];   // [k][c]  c<64: z-row, c>=64: hi-row

    const int m0  = blockIdx.y * 128;
    const int h0  = blockIdx.x * 64;
    const int tid = threadIdx.x;
    const int tx  = tid & 15;        // channel group 0..15 (4 channels each)
    const int ty  = tid >> 4;        // row group 0..15 (8 rows each)

    float accz[8][4];
    float acch[8][4];
#pragma unroll
    for (int i = 0; i < 8; i++)
#pragma unroll
        for (int j = 0; j < 4; j++) { accz[i][j] = 0.f; acch[i][j] = 0.f; }

    for (int kt = 0; kt < HIN / 16; ++kt) {
        // --- stage A tile: x[m0 + r][kt*16 + kk] -> As[kk][r]
#pragma unroll
        for (int q = 0; q < 2; q++) {
            int flat = tid * 2 + q;          // 0..511 float4s
            int r    = flat >> 2;            // 0..127
            int kk4  = (flat & 3) * 4;       // 0,4,8,12
            float4 v = *(const float4*)(x + (size_t)(m0 + r) * HIN + kt * 16 + kk4);
            As[(kk4 + 0) * 128 + r] = v.x;
            As[(kk4 + 1) * 128 + r] = v.y;
            As[(kk4 + 2) * 128 + r] = v.z;
            As[(kk4 + 3) * 128 + r] = v.w;
        }
        // --- stage B tile: W rows (h0..h0+63) and (HD+h0..HD+h0+63)
#pragma unroll
        for (int q = 0; q < 2; q++) {
            int flat = tid * 2 + q;
            int c    = flat >> 2;            // 0..127 combined column
            int kk4  = (flat & 3) * 4;
            int row  = (c < 64) ? (h0 + c) : (HD + h0 + (c - 64));
            float4 v = *(const float4*)(W + (size_t)row * HIN + kt * 16 + kk4);
            Bs[(kk4 + 0) * 128 + c] = v.x;
            Bs[(kk4 + 1) * 128 + c] = v.y;
            Bs[(kk4 + 2) * 128 + c] = v.z;
            Bs[(kk4 + 3) * 128 + c] = v.w;
        }
        __syncthreads();

#pragma unroll
        for (int kk = 0; kk < 16; kk++) {
            float4 a0 = *(const float4*)&As[kk * 128 + ty * 8];
            float4 a1 = *(const float4*)&As[kk * 128 + ty * 8 + 4];
            float4 vz = *(const float4*)&Bs[kk * 128 + tx * 4];
            float4 vh = *(const float4*)&Bs[kk * 128 + 64 + tx * 4];
            float ar[8] = {a0.x, a0.y, a0.z, a0.w, a1.x, a1.y, a1.z, a1.w};
            float bz[4] = {vz.x, vz.y, vz.z, vz.w};
            float bh[4] = {vh.x, vh.y, vh.z, vh.w};
#pragma unroll
            for (int i = 0; i < 8; i++)
#pragma unroll
                for (int j = 0; j < 4; j++) {
                    accz[i][j] = fmaf(ar[i], bz[j], accz[i][j]);
                    acch[i][j] = fmaf(ar[i], bh[j], acch[i][j]);
                }
        }
        __syncthreads();
    }

    // --- epilogue: bias + log-space activations, write scan coefficients
#pragma unroll
    for (int i = 0; i < 8; i++) {
        int m = m0 + ty * 8 + i;
#pragma unroll
        for (int j = 0; j < 4; j++) {
            int ch = h0 + tx * 4 + j;
            float z  = accz[i][j] + bias[ch];
            float hi = acch[i][j] + bias[HD + ch];
            float log_z = -softplusf(-z);   // log sigmoid(z)
            float log_c = -softplusf(z);    // log (1 - sigmoid(z))
            float ltH = (hi >= 0.f) ? __logf(hi + 0.5f) : -softplusf(-hi);
            size_t idx = (size_t)m * HD + ch;
            g_a[idx] = log_c;
            g_b[idx] = log_z + ltH;
        }
    }
}

// ---------------------------------------------------------------------------
// Kernel 2: sequential log-space scan. One thread per (n, h) chain:
//   log_h_t = logaddexp(a_t + log_h_{t-1}, b_t);  out_t = exp(log_h_t)
// Mathematically identical to the reference's a_star + cumlogsumexp form
// (and more numerically stable). Loads are stride-HD per step but coalesced
// across the warp (consecutive h). unroll 4 lets ptxas front-batch the
// independent loads of the group (MLP ~ 8).
// ---------------------------------------------------------------------------
__global__ __launch_bounds__(256) void scan_kernel(
    const float* __restrict__ hx,   // (NB, HD)
    float* __restrict__ out)        // (NB, LSEQ, HD)
{
    int t = blockIdx.x * blockDim.x + threadIdx.x;   // 0..8191
    if (t >= NB * HD) return;
    int n = t >> 10;
    int h = t & (HD - 1);

    float logh = __logf(hx[t]);

    const float* pa = g_a + (size_t)n * LSEQ * HD + h;
    const float* pb = g_b + (size_t)n * LSEQ * HD + h;
    float*       po = out + (size_t)n * LSEQ * HD + h;

#pragma unroll 4
    for (int l = 0; l < LSEQ; l++) {
        float A  = pa[(size_t)l * HD];
        float Bv = pb[(size_t)l * HD];
        float u  = A + logh;
        float mx = fmaxf(u, Bv);
        float mn = fminf(u, Bv);
        logh = mx + log1pf(__expf(mn - mx));
        po[(size_t)l * HD] = __expf(logh);
    }
}

extern "C" void kernel_launch(void* const* d_in, const int* in_sizes, int n_in,
                              void* d_out, int out_size) {
    const float* x    = (const float*)d_in[0];   // (8, 4096, 1024)
    const float* W    = (const float*)d_in[1];   // (2048, 1024)
    const float* bias = (const float*)d_in[2];   // (2048,)
    const float* hx   = (const float*)d_in[3];   // (8, 1024)
    float* out = (float*)d_out;                  // (8, 4096, 1024)

    dim3 grid(HD / 64, MTOT / 128);              // (16, 256)
    gemm_act_kernel<<<grid, 256>>>(x, W, bias);

    scan_kernel<<<(NB * HD) / 256, 256>>>(hx, out);
}

// round 3
// speedup vs baseline: 1.7292x; 1.7292x over previous
#include <cuda_runtime.h>
#include <math.h>
#include <stdint.h>

#define NB    8
#define LSEQ  4096
#define HIN   1024
#define HD    1024
#define MTOT  (NB * LSEQ)        // 32768

#define BM    128                // M per CTA
#define BNC   256                // combined N per CTA (128 z + 128 h_inter)
#define BNR   128                // real channels per CTA
#define BK    32                 // K per stage
#define STAGES 3
#define KIT   (HIN / BK)         // 32

#define PITCHW 36                // smem words per row (144 B: conflict-free + 16B aligned)
#define AWORDS (BM * PITCHW)     // 4608
#define BWORDS (BNC * PITCHW)    // 9216
#define STAGEW (AWORDS + BWORDS) // 13824 words
#define SMEM_BYTES (STAGES * STAGEW * 4)   // 165888
#define EPIPITCH 258

// Static scratch (no runtime allocation allowed)
__device__ float g_xt[(size_t)MTOT * HIN];        // tf32-rounded x
__device__ float g_wt[(size_t)2 * HD * HIN];      // tf32-rounded W
__device__ float g_a [(size_t)MTOT * HD];         // log_coeffs
__device__ float g_b [(size_t)MTOT * HD];         // log_z + log_g(h_inter)

__device__ __forceinline__ float tf32r(float f) {
    uint32_t r; asm("cvt.rna.tf32.f32 %0, %1;" : "=r"(r) : "f"(f));
    return __uint_as_float(r);
}
__device__ __forceinline__ uint32_t smem_u32(const void* p) {
    uint32_t a;
    asm("{ .reg .u64 t; cvta.to.shared.u64 t, %1; cvt.u32.u64 %0, t; }" : "=r"(a) : "l"(p));
    return a;
}
__device__ __forceinline__ void cp16(uint32_t dst, const void* src) {
    asm volatile("cp.async.cg.shared.global [%0], [%1], 16;" :: "r"(dst), "l"(src) : "memory");
}
__device__ __forceinline__ float softplusf(float v) {
    return v > 20.f ? v : log1pf(__expf(v));
}

// ---------------------------------------------------------------------------
// Pre-convert x, W to tf32 (RNA) in scratch
// ---------------------------------------------------------------------------
__global__ void __launch_bounds__(256) cvt_kernel(
    const float* __restrict__ x, const float* __restrict__ W)
{
    size_t i = (size_t)blockIdx.x * blockDim.x + threadIdx.x;
    size_t stride = (size_t)gridDim.x * blockDim.x;
    const float4* x4 = (const float4*)x;
    float4* xo = (float4*)g_xt;
    size_t nx = (size_t)MTOT * HIN / 4;
    for (size_t j = i; j < nx; j += stride) {
        float4 v = x4[j];
        v.x = tf32r(v.x); v.y = tf32r(v.y); v.z = tf32r(v.z); v.w = tf32r(v.w);
        xo[j] = v;
    }
    const float4* w4 = (const float4*)W;
    float4* wo = (float4*)g_wt;
    size_t nw = (size_t)2 * HD * HIN / 4;
    for (size_t j = i; j < nw; j += stride) {
        float4 v = w4[j];
        v.x = tf32r(v.x); v.y = tf32r(v.y); v.z = tf32r(v.z); v.w = tf32r(v.w);
        wo[j] = v;
    }
}

// ---------------------------------------------------------------------------
// tf32 mma.sync GEMM + fused log-space activation epilogue
// ---------------------------------------------------------------------------
__global__ void __launch_bounds__(256, 1) gemm_kernel(const float* __restrict__ bias)
{
    extern __shared__ float sm[];
    const int tid  = threadIdx.x;
    const int wid  = tid >> 5;
    const int lane = tid & 31;
    const int g    = lane >> 2;       // groupID
    const int c    = lane & 3;        // threadID in group
    const int m0   = blockIdx.y * BM;
    const int h0   = blockIdx.x * BNR;
    const uint32_t sbase = smem_u32(sm);

    // cp.async chunk descriptors: A 4/thread, B 8/thread (16B chunks)
    const float* gA[4]; uint32_t dA[4];
#pragma unroll
    for (int i = 0; i < 4; i++) {
        int ci = tid + i * 256;           // 0..1023
        int row = ci >> 3, ch = ci & 7;
        gA[i] = g_xt + (size_t)(m0 + row) * HIN + ch * 4;
        dA[i] = (uint32_t)(row * PITCHW + ch * 4) * 4;
    }
    const float* gB[8]; uint32_t dB[8];
#pragma unroll
    for (int i = 0; i < 8; i++) {
        int ci = tid + i * 256;           // 0..2047
        int row = ci >> 3, ch = ci & 7;
        int wrow = (row < 128) ? (h0 + row) : (HD + h0 + row - 128);
        gB[i] = g_wt + (size_t)wrow * HIN + ch * 4;
        dB[i] = (uint32_t)(row * PITCHW + ch * 4) * 4;
    }

#define ISSUE(KT) do {                                                        \
    int _kt = (KT);                                                           \
    if (_kt < KIT) {                                                          \
        uint32_t _s = sbase + (uint32_t)(_kt % STAGES) * (STAGEW * 4);        \
        _Pragma("unroll")                                                     \
        for (int _i = 0; _i < 4; _i++) cp16(_s + dA[_i], gA[_i] + _kt * BK);  \
        uint32_t _sb = _s + AWORDS * 4;                                       \
        _Pragma("unroll")                                                     \
        for (int _i = 0; _i < 8; _i++) cp16(_sb + dB[_i], gB[_i] + _kt * BK); \
    }                                                                         \
    asm volatile("cp.async.commit_group;" ::: "memory");                      \
} while (0)

    ISSUE(0);
    ISSUE(1);

    // 8 warps: 2(M) x 4(Ncomb); warp tile 64x64 -> 4 Mtiles x 8 Ntiles
    const int mw = (wid >> 2) * 64;
    const int nw = (wid & 3) * 64;
    float d[4][8][4];
#pragma unroll
    for (int mt = 0; mt < 4; mt++)
#pragma unroll
        for (int nt = 0; nt < 8; nt++)
#pragma unroll
            for (int q = 0; q < 4; q++) d[mt][nt][q] = 0.f;

    for (int kt = 0; kt < KIT; kt++) {
        asm volatile("cp.async.wait_group 1;" ::: "memory");
        __syncthreads();
        ISSUE(kt + 2);

        const float* sa = sm + (kt % STAGES) * STAGEW;
        const float* sb = sa + AWORDS;

#pragma unroll
        for (int k8 = 0; k8 < 4; k8++) {
            const int k = k8 * 8;
            uint32_t af[4][4], bf[8][2];
#pragma unroll
            for (int mt = 0; mt < 4; mt++) {
                const float* p = sa + (mw + mt * 16 + g) * PITCHW + k + c;
                af[mt][0] = __float_as_uint(p[0]);
                af[mt][1] = __float_as_uint(p[8 * PITCHW]);
                af[mt][2] = __float_as_uint(p[4]);
                af[mt][3] = __float_as_uint(p[8 * PITCHW + 4]);
            }
#pragma unroll
            for (int nt = 0; nt < 8; nt++) {
                const float* p = sb + (nw + nt * 8 + g) * PITCHW + k + c;
                bf[nt][0] = __float_as_uint(p[0]);
                bf[nt][1] = __float_as_uint(p[4]);
            }
#pragma unroll
            for (int mt = 0; mt < 4; mt++)
#pragma unroll
                for (int nt = 0; nt < 8; nt++) {
                    asm volatile(
                        "mma.sync.aligned.m16n8k8.row.col.f32.tf32.tf32.f32 "
                        "{%0,%1,%2,%3}, {%4,%5,%6,%7}, {%8,%9}, {%0,%1,%2,%3};"
                        : "+f"(d[mt][nt][0]), "+f"(d[mt][nt][1]),
                          "+f"(d[mt][nt][2]), "+f"(d[mt][nt][3])
                        : "r"(af[mt][0]), "r"(af[mt][1]), "r"(af[mt][2]), "r"(af[mt][3]),
                          "r"(bf[nt][0]), "r"(bf[nt][1]));
                }
        }
    }
    __syncthreads();

    // ---- epilogue: acc -> smem (pitch 258) -> pair z/h_inter -> activations
#pragma unroll
    for (int mt = 0; mt < 4; mt++)
#pragma unroll
        for (int nt = 0; nt < 8; nt++) {
            int r   = mw + mt * 16 + g;
            int col = nw + nt * 8 + 2 * c;
            *(float2*)&sm[r * EPIPITCH + col]       = make_float2(d[mt][nt][0], d[mt][nt][1]);
            *(float2*)&sm[(r + 8) * EPIPITCH + col] = make_float2(d[mt][nt][2], d[mt][nt][3]);
        }
    __syncthreads();

#pragma unroll 4
    for (int it = 0; it < 64; it++) {
        int flat = it * 256 + tid;
        int m  = flat >> 7;
        int ch = flat & 127;
        float z  = sm[m * EPIPITCH + ch]       + __ldg(bias + h0 + ch);
        float hi = sm[m * EPIPITCH + 128 + ch] + __ldg(bias + HD + h0 + ch);
        float log_z = -softplusf(-z);
        float log_c = -softplusf(z);
        float ltH   = (hi >= 0.f) ? __logf(hi + 0.5f) : -softplusf(-hi);
        size_t idx = (size_t)(m0 + m) * HD + h0 + ch;
        g_a[idx] = log_c;
        g_b[idx] = log_z + ltH;
    }
}

// ---------------------------------------------------------------------------
// Sequential log-space scan: one thread per (n,h) chain
// ---------------------------------------------------------------------------
__global__ void __launch_bounds__(256) scan_kernel(
    const float* __restrict__ hx, float* __restrict__ out)
{
    int t = blockIdx.x * blockDim.x + threadIdx.x;
    if (t >= NB * HD) return;
    int n = t >> 10;
    int h = t & (HD - 1);

    float logh = __logf(hx[t]);
    const float* pa = g_a + (size_t)n * LSEQ * HD + h;
    const float* pb = g_b + (size_t)n * LSEQ * HD + h;
    float*       po = out + (size_t)n * LSEQ * HD + h;

#pragma unroll 4
    for (int l = 0; l < LSEQ; l++) {
        float A  = pa[(size_t)l * HD];
        float Bv = pb[(size_t)l * HD];
        float u  = A + logh;
        float mx = fmaxf(u, Bv);
        float mn = fminf(u, Bv);
        logh = mx + log1pf(__expf(mn - mx));
        po[(size_t)l * HD] = __expf(logh);
    }
}

extern "C" void kernel_launch(void* const* d_in, const int* in_sizes, int n_in,
                              void* d_out, int out_size) {
    const float* x    = (const float*)d_in[0];
    const float* W    = (const float*)d_in[1];
    const float* bias = (const float*)d_in[2];
    const float* hx   = (const float*)d_in[3];
    float* out = (float*)d_out;

    cudaFuncSetAttribute(gemm_kernel,
                         cudaFuncAttributeMaxDynamicSharedMemorySize, SMEM_BYTES);

    cvt_kernel<<<2048, 256>>>(x, W);
    dim3 grid(HD / BNR, MTOT / BM);   // (8, 256)
    gemm_kernel<<<grid, 256, SMEM_BYTES>>>(bias);
    scan_kernel<<<(NB * HD) / 256, 256>>>(hx, out);
}

// round 4
// speedup vs baseline: 1.8190x; 1.0519x over previous
#include <cuda_runtime.h>
#include <math.h>
#include <stdint.h>

#define NB    8
#define LSEQ  4096
#define HIN   1024
#define HD    1024
#define MTOT  (NB * LSEQ)        // 32768

#define BM    128                // M per CTA
#define BNC   256                // combined N per CTA (128 z + 128 h_inter)
#define BNR   128                // real channels per CTA
#define BK    32                 // K per stage
#define STAGES 3
#define KIT   (HIN / BK)         // 32
#define NTHR  512

#define PITCHW 36                // smem words per row (144 B: conflict-free + 16B aligned)
#define AWORDS (BM * PITCHW)     // 4608
#define BWORDS (BNC * PITCHW)    // 9216
#define STAGEW (AWORDS + BWORDS) // 13824 words
#define SMEM_BYTES (STAGES * STAGEW * 4)   // 165888
#define EPIPITCH 258

// Static scratch (no runtime allocation allowed)
__device__ float g_xt[(size_t)MTOT * HIN];        // tf32-rounded x
__device__ float g_wt[(size_t)2 * HD * HIN];      // tf32-rounded W
__device__ float g_a [(size_t)MTOT * HD];         // log_coeffs
__device__ float g_b [(size_t)MTOT * HD];         // log_z + log_g(h_inter)

__device__ __forceinline__ float tf32r(float f) {
    uint32_t r; asm("cvt.rna.tf32.f32 %0, %1;" : "=r"(r) : "f"(f));
    return __uint_as_float(r);
}
__device__ __forceinline__ uint32_t smem_u32(const void* p) {
    uint32_t a;
    asm("{ .reg .u64 t; cvta.to.shared.u64 t, %1; cvt.u32.u64 %0, t; }" : "=r"(a) : "l"(p));
    return a;
}
__device__ __forceinline__ void cp16(uint32_t dst, const void* src) {
    asm volatile("cp.async.cg.shared.global [%0], [%1], 16;" :: "r"(dst), "l"(src) : "memory");
}
__device__ __forceinline__ float softplusf(float v) {
    return v > 20.f ? v : log1pf(__expf(v));
}

// ---------------------------------------------------------------------------
// Pre-convert x, W to tf32 (RNA) in scratch
// ---------------------------------------------------------------------------
__global__ void __launch_bounds__(256) cvt_kernel(
    const float* __restrict__ x, const float* __restrict__ W)
{
    size_t i = (size_t)blockIdx.x * blockDim.x + threadIdx.x;
    size_t stride = (size_t)gridDim.x * blockDim.x;
    const float4* x4 = (const float4*)x;
    float4* xo = (float4*)g_xt;
    size_t nx = (size_t)MTOT * HIN / 4;
    for (size_t j = i; j < nx; j += stride) {
        float4 v = x4[j];
        v.x = tf32r(v.x); v.y = tf32r(v.y); v.z = tf32r(v.z); v.w = tf32r(v.w);
        xo[j] = v;
    }
    const float4* w4 = (const float4*)W;
    float4* wo = (float4*)g_wt;
    size_t nw = (size_t)2 * HD * HIN / 4;
    for (size_t j = i; j < nw; j += stride) {
        float4 v = w4[j];
        v.x = tf32r(v.x); v.y = tf32r(v.y); v.z = tf32r(v.z); v.w = tf32r(v.w);
        wo[j] = v;
    }
}

// ---------------------------------------------------------------------------
// tf32 mma.sync GEMM + fused log-space activation epilogue
// 512 threads = 16 warps (4/SMSP) for latency hiding; warp tile 32 x 64comb
// ---------------------------------------------------------------------------
__global__ void __launch_bounds__(NTHR, 1) gemm_kernel(const float* __restrict__ bias)
{
    extern __shared__ float sm[];
    const int tid  = threadIdx.x;
    const int wid  = tid >> 5;
    const int lane = tid & 31;
    const int g    = lane >> 2;       // groupID
    const int c    = lane & 3;        // threadID in group
    const int m0   = blockIdx.y * BM;
    const int h0   = blockIdx.x * BNR;
    const uint32_t sbase = smem_u32(sm);

    // cp.async chunk descriptors: A 2/thread, B 4/thread (16B chunks)
    const float* gA[2]; uint32_t dA[2];
#pragma unroll
    for (int i = 0; i < 2; i++) {
        int ci = tid + i * NTHR;          // 0..1023
        int row = ci >> 3, ch = ci & 7;
        gA[i] = g_xt + (size_t)(m0 + row) * HIN + ch * 4;
        dA[i] = (uint32_t)(row * PITCHW + ch * 4) * 4;
    }
    const float* gB[4]; uint32_t dB[4];
#pragma unroll
    for (int i = 0; i < 4; i++) {
        int ci = tid + i * NTHR;          // 0..2047
        int row = ci >> 3, ch = ci & 7;
        int wrow = (row < 128) ? (h0 + row) : (HD + h0 + row - 128);
        gB[i] = g_wt + (size_t)wrow * HIN + ch * 4;
        dB[i] = (uint32_t)(row * PITCHW + ch * 4) * 4;
    }

#define ISSUE(KT) do {                                                        \
    int _kt = (KT);                                                           \
    if (_kt < KIT) {                                                          \
        uint32_t _s = sbase + (uint32_t)(_kt % STAGES) * (STAGEW * 4);        \
        _Pragma("unroll")                                                     \
        for (int _i = 0; _i < 2; _i++) cp16(_s + dA[_i], gA[_i] + _kt * BK);  \
        uint32_t _sb = _s + AWORDS * 4;                                       \
        _Pragma("unroll")                                                     \
        for (int _i = 0; _i < 4; _i++) cp16(_sb + dB[_i], gB[_i] + _kt * BK); \
    }                                                                         \
    asm volatile("cp.async.commit_group;" ::: "memory");                      \
} while (0)

    ISSUE(0);
    ISSUE(1);

    // 16 warps: 4(M) x 4(Ncomb); warp tile 32 x 64 -> 2 Mtiles x 8 Ntiles
    const int mw = (wid >> 2) * 32;
    const int nw = (wid & 3) * 64;
    float d[2][8][4];
#pragma unroll
    for (int mt = 0; mt < 2; mt++)
#pragma unroll
        for (int nt = 0; nt < 8; nt++)
#pragma unroll
            for (int q = 0; q < 4; q++) d[mt][nt][q] = 0.f;

    for (int kt = 0; kt < KIT; kt++) {
        asm volatile("cp.async.wait_group 1;" ::: "memory");
        __syncthreads();
        ISSUE(kt + 2);

        const float* sa = sm + (kt % STAGES) * STAGEW;
        const float* sb = sa + AWORDS;

#pragma unroll
        for (int k8 = 0; k8 < 4; k8++) {
            const int k = k8 * 8;
            uint32_t af[2][4], bf[8][2];
#pragma unroll
            for (int mt = 0; mt < 2; mt++) {
                const float* p = sa + (mw + mt * 16 + g) * PITCHW + k + c;
                af[mt][0] = __float_as_uint(p[0]);
                af[mt][1] = __float_as_uint(p[8 * PITCHW]);
                af[mt][2] = __float_as_uint(p[4]);
                af[mt][3] = __float_as_uint(p[8 * PITCHW + 4]);
            }
#pragma unroll
            for (int nt = 0; nt < 8; nt++) {
                const float* p = sb + (nw + nt * 8 + g) * PITCHW + k + c;
                bf[nt][0] = __float_as_uint(p[0]);
                bf[nt][1] = __float_as_uint(p[4]);
            }
#pragma unroll
            for (int mt = 0; mt < 2; mt++)
#pragma unroll
                for (int nt = 0; nt < 8; nt++) {
                    asm volatile(
                        "mma.sync.aligned.m16n8k8.row.col.f32.tf32.tf32.f32 "
                        "{%0,%1,%2,%3}, {%4,%5,%6,%7}, {%8,%9}, {%0,%1,%2,%3};"
                        : "+f"(d[mt][nt][0]), "+f"(d[mt][nt][1]),
                          "+f"(d[mt][nt][2]), "+f"(d[mt][nt][3])
                        : "r"(af[mt][0]), "r"(af[mt][1]), "r"(af[mt][2]), "r"(af[mt][3]),
                          "r"(bf[nt][0]), "r"(bf[nt][1]));
                }
        }
    }
    __syncthreads();

    // ---- epilogue: acc -> smem (pitch 258) -> pair z/h_inter -> activations
#pragma unroll
    for (int mt = 0; mt < 2; mt++)
#pragma unroll
        for (int nt = 0; nt < 8; nt++) {
            int r   = mw + mt * 16 + g;
            int col = nw + nt * 8 + 2 * c;
            *(float2*)&sm[r * EPIPITCH + col]       = make_float2(d[mt][nt][0], d[mt][nt][1]);
            *(float2*)&sm[(r + 8) * EPIPITCH + col] = make_float2(d[mt][nt][2], d[mt][nt][3]);
        }
    __syncthreads();

#pragma unroll 4
    for (int it = 0; it < 32; it++) {
        int flat = it * NTHR + tid;
        int m  = flat >> 7;
        int ch = flat & 127;
        float z  = sm[m * EPIPITCH + ch]       + __ldg(bias + h0 + ch);
        float hi = sm[m * EPIPITCH + 128 + ch] + __ldg(bias + HD + h0 + ch);
        float log_z = -softplusf(-z);
        float log_c = -softplusf(z);
        float ltH   = (hi >= 0.f) ? __logf(hi + 0.5f) : -softplusf(-hi);
        size_t idx = (size_t)(m0 + m) * HD + h0 + ch;
        g_a[idx] = log_c;
        g_b[idx] = log_z + ltH;
    }
}

// ---------------------------------------------------------------------------
// Sequential log-space scan: one thread per (n,h) chain
// ---------------------------------------------------------------------------
__global__ void __launch_bounds__(256) scan_kernel(
    const float* __restrict__ hx, float* __restrict__ out)
{
    int t = blockIdx.x * blockDim.x + threadIdx.x;
    if (t >= NB * HD) return;
    int n = t >> 10;
    int h = t & (HD - 1);

    float logh = __logf(hx[t]);
    const float* pa = g_a + (size_t)n * LSEQ * HD + h;
    const float* pb = g_b + (size_t)n * LSEQ * HD + h;
    float*       po = out + (size_t)n * LSEQ * HD + h;

#pragma unroll 4
    for (int l = 0; l < LSEQ; l++) {
        float A  = pa[(size_t)l * HD];
        float Bv = pb[(size_t)l * HD];
        float u  = A + logh;
        float mx = fmaxf(u, Bv);
        float mn = fminf(u, Bv);
        logh = mx + log1pf(__expf(mn - mx));
        po[(size_t)l * HD] = __expf(logh);
    }
}

extern "C" void kernel_launch(void* const* d_in, const int* in_sizes, int n_in,
                              void* d_out, int out_size) {
    const float* x    = (const float*)d_in[0];
    const float* W    = (const float*)d_in[1];
    const float* bias = (const float*)d_in[2];
    const float* hx   = (const float*)d_in[3];
    float* out = (float*)d_out;

    cudaFuncSetAttribute(gemm_kernel,
                         cudaFuncAttributeMaxDynamicSharedMemorySize, SMEM_BYTES);

    cvt_kernel<<<2048, 256>>>(x, W);
    dim3 grid(HD / BNR, MTOT / BM);   // (8, 256)
    gemm_kernel<<<grid, NTHR, SMEM_BYTES>>>(bias);
    scan_kernel<<<(NB * HD) / 256, 256>>>(hx, out);
}

// round 5
// speedup vs baseline: 2.2014x; 1.2103x over previous
#include <cuda_runtime.h>
#include <cuda_fp16.h>
#include <math.h>
#include <stdint.h>

#define NB    8
#define LSEQ  4096
#define HIN   1024
#define HD    1024
#define MTOT  (NB * LSEQ)        // 32768

#define BM    128                // M per CTA
#define BNC   256                // combined N per CTA (128 z + 128 h_inter)
#define BNR   128                // real channels per CTA
#define BK    64                 // fp16 K elements per stage (128 B rows)
#define STAGES 3
#define KIT   (HIN / BK)         // 16
#define NTHR  512

#define PITCHH 72                // halves per smem row (144 B: conflict-free, 16B-mult)
#define AHALF  (BM * PITCHH)     // 9216
#define BHALF  (BNC * PITCHH)    // 18432
#define STAGEH (AHALF + BHALF)   // 27648 halves = 55296 B
#define SMEM_BYTES (STAGES * STAGEH * 2)   // 165888
#define EPIPITCH 258

// Static scratch (no runtime allocation allowed)
__device__ __half g_xh[(size_t)MTOT * HIN];       // fp16 x
__device__ __half g_wh[(size_t)2 * HD * HIN];     // fp16 W
__device__ float  g_a [(size_t)MTOT * HD];        // log_coeffs
__device__ float  g_b [(size_t)MTOT * HD];        // log_z + log_g(h_inter)

__device__ __forceinline__ uint32_t smem_u32(const void* p) {
    uint32_t a;
    asm("{ .reg .u64 t; cvta.to.shared.u64 t, %1; cvt.u32.u64 %0, t; }" : "=r"(a) : "l"(p));
    return a;
}
__device__ __forceinline__ void cp16(uint32_t dst, const void* src) {
    asm volatile("cp.async.cg.shared.global [%0], [%1], 16;" :: "r"(dst), "l"(src) : "memory");
}
__device__ __forceinline__ float softplusf(float v) {
    return v > 20.f ? v : log1pf(__expf(v));
}

// ---------------------------------------------------------------------------
// Pre-convert x, W to fp16 (rn)
// ---------------------------------------------------------------------------
__global__ void __launch_bounds__(256) cvt_kernel(
    const float* __restrict__ x, const float* __restrict__ W)
{
    size_t i = (size_t)blockIdx.x * blockDim.x + threadIdx.x;
    size_t stride = (size_t)gridDim.x * blockDim.x;
    const float4* x4 = (const float4*)x;
    __half2* xo = (__half2*)g_xh;
    size_t nx = (size_t)MTOT * HIN / 4;
    for (size_t j = i; j < nx; j += stride) {
        float4 v = x4[j];
        xo[j * 2 + 0] = __floats2half2_rn(v.x, v.y);
        xo[j * 2 + 1] = __floats2half2_rn(v.z, v.w);
    }
    const float4* w4 = (const float4*)W;
    __half2* wo = (__half2*)g_wh;
    size_t nw = (size_t)2 * HD * HIN / 4;
    for (size_t j = i; j < nw; j += stride) {
        float4 v = w4[j];
        wo[j * 2 + 0] = __floats2half2_rn(v.x, v.y);
        wo[j * 2 + 1] = __floats2half2_rn(v.z, v.w);
    }
}

// ---------------------------------------------------------------------------
// fp16 mma.sync (m16n8k16) GEMM + fused log-space activation epilogue
// 512 threads / 16 warps; warp tile 32 x 64comb
// ---------------------------------------------------------------------------
__global__ void __launch_bounds__(NTHR, 1) gemm_kernel(const float* __restrict__ bias)
{
    extern __shared__ __half smh[];
    float* smf = (float*)smh;
    const int tid  = threadIdx.x;
    const int wid  = tid >> 5;
    const int lane = tid & 31;
    const int g    = lane >> 2;       // groupID
    const int c    = lane & 3;        // threadID in group
    const int m0   = blockIdx.y * BM;
    const int h0   = blockIdx.x * BNR;
    const uint32_t sbase = smem_u32(smh);

    // cp.async chunk descriptors (16B = 8 halves): A 2/thread, B 4/thread
    const __half* gA[2]; uint32_t dA[2];
#pragma unroll
    for (int i = 0; i < 2; i++) {
        int ci = tid + i * NTHR;          // 0..1023
        int row = ci >> 3, ch = ci & 7;
        gA[i] = g_xh + (size_t)(m0 + row) * HIN + ch * 8;
        dA[i] = (uint32_t)(row * 144 + ch * 16);
    }
    const __half* gB[4]; uint32_t dB[4];
#pragma unroll
    for (int i = 0; i < 4; i++) {
        int ci = tid + i * NTHR;          // 0..2047
        int row = ci >> 3, ch = ci & 7;
        int wrow = (row < 128) ? (h0 + row) : (HD + h0 + row - 128);
        gB[i] = g_wh + (size_t)wrow * HIN + ch * 8;
        dB[i] = (uint32_t)(AHALF * 2 + row * 144 + ch * 16);
    }

#define ISSUE(KT) do {                                                        \
    int _kt = (KT);                                                           \
    if (_kt < KIT) {                                                          \
        uint32_t _s = sbase + (uint32_t)(_kt % STAGES) * (STAGEH * 2);        \
        _Pragma("unroll")                                                     \
        for (int _i = 0; _i < 2; _i++) cp16(_s + dA[_i], gA[_i] + _kt * BK);  \
        _Pragma("unroll")                                                     \
        for (int _i = 0; _i < 4; _i++) cp16(_s + dB[_i], gB[_i] + _kt * BK);  \
    }                                                                         \
    asm volatile("cp.async.commit_group;" ::: "memory");                      \
} while (0)

    ISSUE(0);
    ISSUE(1);

    // 16 warps: 4(M) x 4(Ncomb); warp tile 32 x 64 -> 2 Mtiles x 8 Ntiles
    const int mw = (wid >> 2) * 32;
    const int nw = (wid & 3) * 64;
    float d[2][8][4];
#pragma unroll
    for (int mt = 0; mt < 2; mt++)
#pragma unroll
        for (int nt = 0; nt < 8; nt++)
#pragma unroll
            for (int q = 0; q < 4; q++) d[mt][nt][q] = 0.f;

    for (int kt = 0; kt < KIT; kt++) {
        asm volatile("cp.async.wait_group 1;" ::: "memory");
        __syncthreads();
        ISSUE(kt + 2);

        const __half* sa = smh + (kt % STAGES) * STAGEH;
        const __half* sb = sa + AHALF;

#pragma unroll
        for (int s16 = 0; s16 < 4; s16++) {
            const int k = s16 * 16;
            uint32_t af[2][4], bf[8][2];
#pragma unroll
            for (int mt = 0; mt < 2; mt++) {
                const __half* p = sa + (mw + mt * 16 + g) * PITCHH + k + 2 * c;
                af[mt][0] = *(const uint32_t*)(p);
                af[mt][1] = *(const uint32_t*)(p + 8 * PITCHH);
                af[mt][2] = *(const uint32_t*)(p + 8);
                af[mt][3] = *(const uint32_t*)(p + 8 * PITCHH + 8);
            }
#pragma unroll
            for (int nt = 0; nt < 8; nt++) {
                const __half* p = sb + (nw + nt * 8 + g) * PITCHH + k + 2 * c;
                bf[nt][0] = *(const uint32_t*)(p);
                bf[nt][1] = *(const uint32_t*)(p + 8);
            }
#pragma unroll
            for (int mt = 0; mt < 2; mt++)
#pragma unroll
                for (int nt = 0; nt < 8; nt++) {
                    asm volatile(
                        "mma.sync.aligned.m16n8k16.row.col.f32.f16.f16.f32 "
                        "{%0,%1,%2,%3}, {%4,%5,%6,%7}, {%8,%9}, {%0,%1,%2,%3};"
                        : "+f"(d[mt][nt][0]), "+f"(d[mt][nt][1]),
                          "+f"(d[mt][nt][2]), "+f"(d[mt][nt][3])
                        : "r"(af[mt][0]), "r"(af[mt][1]), "r"(af[mt][2]), "r"(af[mt][3]),
                          "r"(bf[nt][0]), "r"(bf[nt][1]));
                }
        }
    }
    __syncthreads();

    // ---- epilogue: acc -> smem (pitch 258) -> pair z/h_inter -> activations
#pragma unroll
    for (int mt = 0; mt < 2; mt++)
#pragma unroll
        for (int nt = 0; nt < 8; nt++) {
            int r   = mw + mt * 16 + g;
            int col = nw + nt * 8 + 2 * c;
            *(float2*)&smf[r * EPIPITCH + col]       = make_float2(d[mt][nt][0], d[mt][nt][1]);
            *(float2*)&smf[(r + 8) * EPIPITCH + col] = make_float2(d[mt][nt][2], d[mt][nt][3]);
        }
    __syncthreads();

#pragma unroll 4
    for (int it = 0; it < 32; it++) {
        int flat = it * NTHR + tid;
        int m  = flat >> 7;
        int ch = flat & 127;
        float z  = smf[m * EPIPITCH + ch]       + __ldg(bias + h0 + ch);
        float hi = smf[m * EPIPITCH + 128 + ch] + __ldg(bias + HD + h0 + ch);
        float log_z = -softplusf(-z);
        float log_c = -softplusf(z);
        float ltH   = (hi >= 0.f) ? __logf(hi + 0.5f) : -softplusf(-hi);
        size_t idx = (size_t)(m0 + m) * HD + h0 + ch;
        g_a[idx] = log_c;
        g_b[idx] = log_z + ltH;
    }
}

// ---------------------------------------------------------------------------
// Sequential log-space scan: one thread per (n,h) chain
// ---------------------------------------------------------------------------
__global__ void __launch_bounds__(256) scan_kernel(
    const float* __restrict__ hx, float* __restrict__ out)
{
    int t = blockIdx.x * blockDim.x + threadIdx.x;
    if (t >= NB * HD) return;
    int n = t >> 10;
    int h = t & (HD - 1);

    float logh = __logf(hx[t]);
    const float* pa = g_a + (size_t)n * LSEQ * HD + h;
    const float* pb = g_b + (size_t)n * LSEQ * HD + h;
    float*       po = out + (size_t)n * LSEQ * HD + h;

#pragma unroll 4
    for (int l = 0; l < LSEQ; l++) {
        float A  = pa[(size_t)l * HD];
        float Bv = pb[(size_t)l * HD];
        float u  = A + logh;
        float mx = fmaxf(u, Bv);
        float mn = fminf(u, Bv);
        logh = mx + log1pf(__expf(mn - mx));
        po[(size_t)l * HD] = __expf(logh);
    }
}

extern "C" void kernel_launch(void* const* d_in, const int* in_sizes, int n_in,
                              void* d_out, int out_size) {
    const float* x    = (const float*)d_in[0];
    const float* W    = (const float*)d_in[1];
    const float* bias = (const float*)d_in[2];
    const float* hx   = (const float*)d_in[3];
    float* out = (float*)d_out;

    cudaFuncSetAttribute(gemm_kernel,
                         cudaFuncAttributeMaxDynamicSharedMemorySize, SMEM_BYTES);

    cvt_kernel<<<2048, 256>>>(x, W);
    dim3 grid(HD / BNR, MTOT / BM);   // (8, 256)
    gemm_kernel<<<grid, NTHR, SMEM_BYTES>>>(bias);
    scan_kernel<<<(NB * HD) / 256, 256>>>(hx, out);
}

// round 6
// speedup vs baseline: 3.0029x; 1.3641x over previous
#include <cuda_runtime.h>
#include <cuda_fp16.h>
#include <math.h>
#include <stdint.h>

#define NB    8
#define LSEQ  4096
#define HIN   1024
#define HD    1024
#define MTOT  (NB * LSEQ)        // 32768

#define BM    128                // M per CTA
#define BNC   256                // combined N per CTA (128 z + 128 h_inter)
#define BNR   128                // real channels per CTA
#define BK    64                 // fp16 K elements per stage (128 B rows)
#define STAGES 3
#define KIT   (HIN / BK)         // 16
#define NTHR  512

#define PITCHH 72                // halves per smem row (144 B)
#define AHALF  (BM * PITCHH)     // 9216
#define BHALF  (BNC * PITCHH)    // 18432
#define STAGEH (AHALF + BHALF)   // 27648 halves = 55296 B
#define SMEM_BYTES (STAGES * STAGEH * 2)   // 165888
#define EPIPITCH 258

// Static scratch (no runtime allocation allowed)
__device__ __half g_xh[(size_t)MTOT * HIN];       // fp16 x
__device__ __half g_wh[(size_t)2 * HD * HIN];     // fp16 W
__device__ float  g_a [(size_t)MTOT * HD];        // log_coeffs
__device__ float  g_b [(size_t)MTOT * HD];        // log_z + log_g(h_inter)

__device__ __forceinline__ uint32_t smem_u32(const void* p) {
    uint32_t a;
    asm("{ .reg .u64 t; cvta.to.shared.u64 t, %1; cvt.u32.u64 %0, t; }" : "=r"(a) : "l"(p));
    return a;
}
__device__ __forceinline__ void cp16(uint32_t dst, const void* src) {
    asm volatile("cp.async.cg.shared.global [%0], [%1], 16;" :: "r"(dst), "l"(src) : "memory");
}
__device__ __forceinline__ void ldsm4(uint32_t& r0, uint32_t& r1, uint32_t& r2, uint32_t& r3,
                                      uint32_t addr) {
    asm volatile("ldmatrix.sync.aligned.m8n8.x4.shared.b16 {%0,%1,%2,%3}, [%4];"
                 : "=r"(r0), "=r"(r1), "=r"(r2), "=r"(r3) : "r"(addr));
}
__device__ __forceinline__ float softplusf(float v) {
    return v > 20.f ? v : log1pf(__expf(v));
}

// ---------------------------------------------------------------------------
// Pre-convert x, W to fp16 (rn)
// ---------------------------------------------------------------------------
__global__ void __launch_bounds__(256) cvt_kernel(
    const float* __restrict__ x, const float* __restrict__ W)
{
    size_t i = (size_t)blockIdx.x * blockDim.x + threadIdx.x;
    size_t stride = (size_t)gridDim.x * blockDim.x;
    const float4* x4 = (const float4*)x;
    __half2* xo = (__half2*)g_xh;
    size_t nx = (size_t)MTOT * HIN / 4;
    for (size_t j = i; j < nx; j += stride) {
        float4 v = x4[j];
        xo[j * 2 + 0] = __floats2half2_rn(v.x, v.y);
        xo[j * 2 + 1] = __floats2half2_rn(v.z, v.w);
    }
    const float4* w4 = (const float4*)W;
    __half2* wo = (__half2*)g_wh;
    size_t nw = (size_t)2 * HD * HIN / 4;
    for (size_t j = i; j < nw; j += stride) {
        float4 v = w4[j];
        wo[j * 2 + 0] = __floats2half2_rn(v.x, v.y);
        wo[j * 2 + 1] = __floats2half2_rn(v.z, v.w);
    }
}

// ---------------------------------------------------------------------------
// fp16 mma.sync (m16n8k16) GEMM, ldmatrix fragments, fused activation epilogue
// ---------------------------------------------------------------------------
__global__ void __launch_bounds__(NTHR, 1) gemm_kernel(const float* __restrict__ bias)
{
    extern __shared__ __half smh[];
    float* smf = (float*)smh;
    const int tid  = threadIdx.x;
    const int wid  = tid >> 5;
    const int lane = tid & 31;
    const int g    = lane >> 2;       // groupID
    const int c    = lane & 3;        // threadID in group
    const int m0   = blockIdx.y * BM;
    const int h0   = blockIdx.x * BNR;
    const uint32_t sbase = smem_u32(smh);

    // cp.async chunk descriptors (16B = 8 halves): A 2/thread, B 4/thread
    const __half* gA[2]; uint32_t dA[2];
#pragma unroll
    for (int i = 0; i < 2; i++) {
        int ci = tid + i * NTHR;          // 0..1023
        int row = ci >> 3, ch = ci & 7;
        gA[i] = g_xh + (size_t)(m0 + row) * HIN + ch * 8;
        dA[i] = (uint32_t)(row * 144 + ch * 16);
    }
    const __half* gB[4]; uint32_t dB[4];
#pragma unroll
    for (int i = 0; i < 4; i++) {
        int ci = tid + i * NTHR;          // 0..2047
        int row = ci >> 3, ch = ci & 7;
        int wrow = (row < 128) ? (h0 + row) : (HD + h0 + row - 128);
        gB[i] = g_wh + (size_t)wrow * HIN + ch * 8;
        dB[i] = (uint32_t)(AHALF * 2 + row * 144 + ch * 16);
    }

#define ISSUE(KT) do {                                                        \
    int _kt = (KT);                                                           \
    if (_kt < KIT) {                                                          \
        uint32_t _s = sbase + (uint32_t)(_kt % STAGES) * (STAGEH * 2);        \
        _Pragma("unroll")                                                     \
        for (int _i = 0; _i < 2; _i++) cp16(_s + dA[_i], gA[_i] + _kt * BK);  \
        _Pragma("unroll")                                                     \
        for (int _i = 0; _i < 4; _i++) cp16(_s + dB[_i], gB[_i] + _kt * BK);  \
    }                                                                         \
    asm volatile("cp.async.commit_group;" ::: "memory");                      \
} while (0)

    ISSUE(0);
    ISSUE(1);

    // 16 warps: 4(M) x 4(Ncomb); warp tile 32 x 64 -> 2 Mtiles x 8 Ntiles
    const int mw = (wid >> 2) * 32;
    const int nw = (wid & 3) * 64;

    // ldmatrix lane-address components (within-stage byte offsets)
    // A x4: matrices {m0k0, m8k0, m0k8, m8k8}; lane j=lane/8 selects matrix
    const int aj = lane >> 3;                       // 0..3
    const int arow = mw + (aj & 1) * 8 + (lane & 7);
    const uint32_t aoff = (uint32_t)(arow * 144 + (aj >> 1) * 16);
    // B x4 covering 2 nt tiles x 2 k-halves: {nt+0 k0, nt+0 k8, nt+1 k0, nt+1 k8}
    const int bj = lane >> 3;
    const int brow_base = nw + (bj >> 1) * 8 + (lane & 7); // + nt*8 added per use
    const uint32_t bkoff = (uint32_t)((bj & 1) * 16);

    float d[2][8][4];
#pragma unroll
    for (int mt = 0; mt < 2; mt++)
#pragma unroll
        for (int nt = 0; nt < 8; nt++)
#pragma unroll
            for (int q = 0; q < 4; q++) d[mt][nt][q] = 0.f;

    for (int kt = 0; kt < KIT; kt++) {
        asm volatile("cp.async.wait_group 1;" ::: "memory");
        __syncthreads();
        ISSUE(kt + 2);

        const uint32_t sa = sbase + (uint32_t)(kt % STAGES) * (STAGEH * 2);
        const uint32_t sb = sa + AHALF * 2;

#pragma unroll
        for (int s16 = 0; s16 < 4; s16++) {
            const uint32_t kbyte = (uint32_t)(s16 * 32);   // 16 halves
            uint32_t af[2][4];
#pragma unroll
            for (int mt = 0; mt < 2; mt++)
                ldsm4(af[mt][0], af[mt][1], af[mt][2], af[mt][3],
                      sa + aoff + (uint32_t)(mt * 16 * 144) + kbyte);

#pragma unroll
            for (int half = 0; half < 2; half++) {
                uint32_t bf[4][2];
#pragma unroll
                for (int p = 0; p < 2; p++) {
                    int ntp = half * 4 + p * 2;     // nt pair base
                    ldsm4(bf[p*2][0], bf[p*2][1], bf[p*2+1][0], bf[p*2+1][1],
                          sb + (uint32_t)((brow_base + ntp * 8) * 144) + bkoff + kbyte);
                }
#pragma unroll
                for (int mt = 0; mt < 2; mt++)
#pragma unroll
                    for (int p = 0; p < 4; p++) {
                        int nt = half * 4 + p;
                        asm volatile(
                            "mma.sync.aligned.m16n8k16.row.col.f32.f16.f16.f32 "
                            "{%0,%1,%2,%3}, {%4,%5,%6,%7}, {%8,%9}, {%0,%1,%2,%3};"
                            : "+f"(d[mt][nt][0]), "+f"(d[mt][nt][1]),
                              "+f"(d[mt][nt][2]), "+f"(d[mt][nt][3])
                            : "r"(af[mt][0]), "r"(af[mt][1]), "r"(af[mt][2]), "r"(af[mt][3]),
                              "r"(bf[p][0]), "r"(bf[p][1]));
                    }
            }
        }
    }
    __syncthreads();

    // ---- epilogue: acc -> smem (pitch 258) -> pair z/h_inter -> activations
#pragma unroll
    for (int mt = 0; mt < 2; mt++)
#pragma unroll
        for (int nt = 0; nt < 8; nt++) {
            int r   = mw + mt * 16 + g;
            int col = nw + nt * 8 + 2 * c;
            *(float2*)&smf[r * EPIPITCH + col]       = make_float2(d[mt][nt][0], d[mt][nt][1]);
            *(float2*)&smf[(r + 8) * EPIPITCH + col] = make_float2(d[mt][nt][2], d[mt][nt][3]);
        }
    __syncthreads();

#pragma unroll 4
    for (int it = 0; it < 32; it++) {
        int flat = it * NTHR + tid;
        int m  = flat >> 7;
        int ch = flat & 127;
        float z  = smf[m * EPIPITCH + ch]       + __ldg(bias + h0 + ch);
        float hi = smf[m * EPIPITCH + 128 + ch] + __ldg(bias + HD + h0 + ch);
        float log_z = -softplusf(-z);
        float log_c = -softplusf(z);
        float ltH   = (hi >= 0.f) ? __logf(hi + 0.5f) : -softplusf(-hi);
        size_t idx = (size_t)(m0 + m) * HD + h0 + ch;
        g_a[idx] = log_c;
        g_b[idx] = log_z + ltH;
    }
}

// ---------------------------------------------------------------------------
// Sequential log-space scan: one thread per (n,h) chain
// logaddexp with fast __logf(1+e^d), d<=0: arg in [1,2], abs err ~1e-6
// ---------------------------------------------------------------------------
__global__ void __launch_bounds__(256) scan_kernel(
    const float* __restrict__ hx, float* __restrict__ out)
{
    int t = blockIdx.x * blockDim.x + threadIdx.x;
    if (t >= NB * HD) return;
    int n = t >> 10;
    int h = t & (HD - 1);

    float logh = __logf(hx[t]);
    const float* pa = g_a + (size_t)n * LSEQ * HD + h;
    const float* pb = g_b + (size_t)n * LSEQ * HD + h;
    float*       po = out + (size_t)n * LSEQ * HD + h;

#pragma unroll 4
    for (int l = 0; l < LSEQ; l++) {
        float A  = pa[(size_t)l * HD];
        float Bv = pb[(size_t)l * HD];
        float u  = A + logh;
        float mx = fmaxf(u, Bv);
        float mn = fminf(u, Bv);
        logh = mx + __logf(1.f + __expf(mn - mx));
        po[(size_t)l * HD] = __expf(logh);
    }
}

extern "C" void kernel_launch(void* const* d_in, const int* in_sizes, int n_in,
                              void* d_out, int out_size) {
    const float* x    = (const float*)d_in[0];
    const float* W    = (const float*)d_in[1];
    const float* bias = (const float*)d_in[2];
    const float* hx   = (const float*)d_in[3];
    float* out = (float*)d_out;

    cudaFuncSetAttribute(gemm_kernel,
                         cudaFuncAttributeMaxDynamicSharedMemorySize, SMEM_BYTES);

    cvt_kernel<<<2048, 256>>>(x, W);
    dim3 grid(HD / BNR, MTOT / BM);   // (8, 256)
    gemm_kernel<<<grid, NTHR, SMEM_BYTES>>>(bias);
    scan_kernel<<<(NB * HD) / 256, 256>>>(hx, out);
}

// round 7
// speedup vs baseline: 4.9115x; 1.6355x over previous
#include <cuda_runtime.h>
#include <cuda_fp16.h>
#include <math.h>
#include <float.h>
#include <stdint.h>

#define NB    8
#define LSEQ  4096
#define HIN   1024
#define HD    1024
#define MTOT  (NB * LSEQ)        // 32768

#define BM    128
#define BNC   256
#define BNR   128
#define BK    64
#define STAGES 3
#define KIT   (HIN / BK)         // 16
#define NTHR  512

#define PITCHH 72
#define AHALF  (BM * PITCHH)     // 9216
#define BHALF  (BNC * PITCHH)    // 18432
#define STAGEH (AHALF + BHALF)   // 27648 halves
#define SMEM_BYTES (STAGES * STAGEH * 2)   // 165888
#define EPIPITCH 258

#define NCH   16                 // scan chunks
#define CHK   (LSEQ / NCH)       // 256

// Static scratch (no runtime allocation allowed)
__device__ __half g_xh[(size_t)MTOT * HIN];
__device__ __half g_wh[(size_t)2 * HD * HIN];
__device__ float  g_a [(size_t)MTOT * HD];     // a_t -> (phase1) prefix P_t
__device__ float  g_b [(size_t)MTOT * HD];     // b_t -> (phase1) chunk-local v_t
__device__ float  g_init[NCH * NB * HD];       // incoming log_h per chunk

__device__ __forceinline__ uint32_t smem_u32(const void* p) {
    uint32_t a;
    asm("{ .reg .u64 t; cvta.to.shared.u64 t, %1; cvt.u32.u64 %0, t; }" : "=r"(a) : "l"(p));
    return a;
}
__device__ __forceinline__ void cp16(uint32_t dst, const void* src) {
    asm volatile("cp.async.cg.shared.global [%0], [%1], 16;" :: "r"(dst), "l"(src) : "memory");
}
__device__ __forceinline__ void ldsm4(uint32_t& r0, uint32_t& r1, uint32_t& r2, uint32_t& r3,
                                      uint32_t addr) {
    asm volatile("ldmatrix.sync.aligned.m8n8.x4.shared.b16 {%0,%1,%2,%3}, [%4];"
                 : "=r"(r0), "=r"(r1), "=r"(r2), "=r"(r3) : "r"(addr));
}
__device__ __forceinline__ float softplusf(float v) {
    return v > 20.f ? v : log1pf(__expf(v));
}
__device__ __forceinline__ float logaddexpf(float u, float v) {
    float mx = fmaxf(u, v), mn = fminf(u, v);
    return mx + __logf(1.f + __expf(mn - mx));
}

// ---------------------------------------------------------------------------
__global__ void __launch_bounds__(256) cvt_kernel(
    const float* __restrict__ x, const float* __restrict__ W)
{
    size_t i = (size_t)blockIdx.x * blockDim.x + threadIdx.x;
    size_t stride = (size_t)gridDim.x * blockDim.x;
    const float4* x4 = (const float4*)x;
    __half2* xo = (__half2*)g_xh;
    size_t nx = (size_t)MTOT * HIN / 4;
    for (size_t j = i; j < nx; j += stride) {
        float4 v = x4[j];
        xo[j * 2 + 0] = __floats2half2_rn(v.x, v.y);
        xo[j * 2 + 1] = __floats2half2_rn(v.z, v.w);
    }
    const float4* w4 = (const float4*)W;
    __half2* wo = (__half2*)g_wh;
    size_t nw = (size_t)2 * HD * HIN / 4;
    for (size_t j = i; j < nw; j += stride) {
        float4 v = w4[j];
        wo[j * 2 + 0] = __floats2half2_rn(v.x, v.y);
        wo[j * 2 + 1] = __floats2half2_rn(v.z, v.w);
    }
}

// ---------------------------------------------------------------------------
// fp16 mma.sync (m16n8k16) GEMM, ldmatrix fragments, fused activation epilogue
// ---------------------------------------------------------------------------
__global__ void __launch_bounds__(NTHR, 1) gemm_kernel(const float* __restrict__ bias)
{
    extern __shared__ __half smh[];
    float* smf = (float*)smh;
    const int tid  = threadIdx.x;
    const int wid  = tid >> 5;
    const int lane = tid & 31;
    const int g    = lane >> 2;
    const int c    = lane & 3;
    const int m0   = blockIdx.y * BM;
    const int h0   = blockIdx.x * BNR;
    const uint32_t sbase = smem_u32(smh);

    const __half* gA[2]; uint32_t dA[2];
#pragma unroll
    for (int i = 0; i < 2; i++) {
        int ci = tid + i * NTHR;
        int row = ci >> 3, ch = ci & 7;
        gA[i] = g_xh + (size_t)(m0 + row) * HIN + ch * 8;
        dA[i] = (uint32_t)(row * 144 + ch * 16);
    }
    const __half* gB[4]; uint32_t dB[4];
#pragma unroll
    for (int i = 0; i < 4; i++) {
        int ci = tid + i * NTHR;
        int row = ci >> 3, ch = ci & 7;
        int wrow = (row < 128) ? (h0 + row) : (HD + h0 + row - 128);
        gB[i] = g_wh + (size_t)wrow * HIN + ch * 8;
        dB[i] = (uint32_t)(AHALF * 2 + row * 144 + ch * 16);
    }

#define ISSUE(KT) do {                                                        \
    int _kt = (KT);                                                           \
    if (_kt < KIT) {                                                          \
        uint32_t _s = sbase + (uint32_t)(_kt % STAGES) * (STAGEH * 2);        \
        _Pragma("unroll")                                                     \
        for (int _i = 0; _i < 2; _i++) cp16(_s + dA[_i], gA[_i] + _kt * BK);  \
        _Pragma("unroll")                                                     \
        for (int _i = 0; _i < 4; _i++) cp16(_s + dB[_i], gB[_i] + _kt * BK);  \
    }                                                                         \
    asm volatile("cp.async.commit_group;" ::: "memory");                      \
} while (0)

    ISSUE(0);
    ISSUE(1);

    const int mw = (wid >> 2) * 32;
    const int nw = (wid & 3) * 64;

    const int aj = lane >> 3;
    const int arow = mw + (aj & 1) * 8 + (lane & 7);
    const uint32_t aoff = (uint32_t)(arow * 144 + (aj >> 1) * 16);
    const int bj = lane >> 3;
    const int brow_base = nw + (bj >> 1) * 8 + (lane & 7);
    const uint32_t bkoff = (uint32_t)((bj & 1) * 16);

    float d[2][8][4];
#pragma unroll
    for (int mt = 0; mt < 2; mt++)
#pragma unroll
        for (int nt = 0; nt < 8; nt++)
#pragma unroll
            for (int q = 0; q < 4; q++) d[mt][nt][q] = 0.f;

    for (int kt = 0; kt < KIT; kt++) {
        asm volatile("cp.async.wait_group 1;" ::: "memory");
        __syncthreads();
        ISSUE(kt + 2);

        const uint32_t sa = sbase + (uint32_t)(kt % STAGES) * (STAGEH * 2);
        const uint32_t sb = sa + AHALF * 2;

#pragma unroll
        for (int s16 = 0; s16 < 4; s16++) {
            const uint32_t kbyte = (uint32_t)(s16 * 32);
            uint32_t af[2][4];
#pragma unroll
            for (int mt = 0; mt < 2; mt++)
                ldsm4(af[mt][0], af[mt][1], af[mt][2], af[mt][3],
                      sa + aoff + (uint32_t)(mt * 16 * 144) + kbyte);

#pragma unroll
            for (int half = 0; half < 2; half++) {
                uint32_t bf[4][2];
#pragma unroll
                for (int p = 0; p < 2; p++) {
                    int ntp = half * 4 + p * 2;
                    ldsm4(bf[p*2][0], bf[p*2][1], bf[p*2+1][0], bf[p*2+1][1],
                          sb + (uint32_t)((brow_base + ntp * 8) * 144) + bkoff + kbyte);
                }
#pragma unroll
                for (int mt = 0; mt < 2; mt++)
#pragma unroll
                    for (int p = 0; p < 4; p++) {
                        int nt = half * 4 + p;
                        asm volatile(
                            "mma.sync.aligned.m16n8k16.row.col.f32.f16.f16.f32 "
                            "{%0,%1,%2,%3}, {%4,%5,%6,%7}, {%8,%9}, {%0,%1,%2,%3};"
                            : "+f"(d[mt][nt][0]), "+f"(d[mt][nt][1]),
                              "+f"(d[mt][nt][2]), "+f"(d[mt][nt][3])
                            : "r"(af[mt][0]), "r"(af[mt][1]), "r"(af[mt][2]), "r"(af[mt][3]),
                              "r"(bf[p][0]), "r"(bf[p][1]));
                    }
            }
        }
    }
    __syncthreads();

#pragma unroll
    for (int mt = 0; mt < 2; mt++)
#pragma unroll
        for (int nt = 0; nt < 8; nt++) {
            int r   = mw + mt * 16 + g;
            int col = nw + nt * 8 + 2 * c;
            *(float2*)&smf[r * EPIPITCH + col]       = make_float2(d[mt][nt][0], d[mt][nt][1]);
            *(float2*)&smf[(r + 8) * EPIPITCH + col] = make_float2(d[mt][nt][2], d[mt][nt][3]);
        }
    __syncthreads();

#pragma unroll 4
    for (int it = 0; it < 32; it++) {
        int flat = it * NTHR + tid;
        int m  = flat >> 7;
        int ch = flat & 127;
        float z  = smf[m * EPIPITCH + ch]       + __ldg(bias + h0 + ch);
        float hi = smf[m * EPIPITCH + 128 + ch] + __ldg(bias + HD + h0 + ch);
        float log_z = -softplusf(-z);
        float log_c = -softplusf(z);
        float ltH   = (hi >= 0.f) ? __logf(hi + 0.5f) : -softplusf(-hi);
        size_t idx = (size_t)(m0 + m) * HD + h0 + ch;
        g_a[idx] = log_c;
        g_b[idx] = log_z + ltH;
    }
}

// ---------------------------------------------------------------------------
// Scan phase 1: per-chunk local scan (init -inf) + a-prefix, in place.
// 131072 threads; coalesced (consecutive threads = consecutive h).
// ---------------------------------------------------------------------------
__global__ void __launch_bounds__(256) scan_p1_kernel()
{
    int t = blockIdx.x * blockDim.x + threadIdx.x;   // 0 .. NB*HD*NCH-1
    int h = t & (HD - 1);
    int r = t >> 10;
    int n = r & (NB - 1);
    int c = r >> 3;                                  // 0..NCH-1

    size_t base = ((size_t)n * LSEQ + (size_t)c * CHK) * HD + h;
    float P = 0.f;
    float v = -FLT_MAX;
#pragma unroll 4
    for (int l = 0; l < CHK; l++) {
        size_t idx = base + (size_t)l * HD;
        float A = g_a[idx];
        float B = g_b[idx];
        P += A;
        v = logaddexpf(A + v, B);
        g_a[idx] = P;
        g_b[idx] = v;
    }
}

// ---------------------------------------------------------------------------
// Scan phase 2: serial composition over NCH chunk summaries per (n,h)
// ---------------------------------------------------------------------------
__global__ void __launch_bounds__(256) scan_p2_kernel(const float* __restrict__ hx)
{
    int t = blockIdx.x * blockDim.x + threadIdx.x;   // 0..NB*HD-1
    if (t >= NB * HD) return;
    int n = t >> 10;
    int h = t & (HD - 1);

    float logh = __logf(hx[t]);
#pragma unroll
    for (int c = 0; c < NCH; c++) {
        g_init[c * (NB * HD) + t] = logh;
        size_t eidx = ((size_t)n * LSEQ + (size_t)c * CHK + (CHK - 1)) * HD + h;
        logh = logaddexpf(g_a[eidx] + logh, g_b[eidx]);
    }
}

// ---------------------------------------------------------------------------
// Scan phase 3: out = exp(logaddexp(P + init, v)), fully parallel, float4
// ---------------------------------------------------------------------------
__global__ void __launch_bounds__(256) scan_p3_kernel(float* __restrict__ out)
{
    size_t i = (size_t)blockIdx.x * blockDim.x + threadIdx.x;
    size_t stride = (size_t)gridDim.x * blockDim.x;
    const float4* pa4 = (const float4*)g_a;
    const float4* pb4 = (const float4*)g_b;
    const float4* pi4 = (const float4*)g_init;
    float4* out4 = (float4*)out;
    size_t total = (size_t)MTOT * HD / 4;

    for (size_t j = i; j < total; j += stride) {
        size_t row = j >> 8;                  // /(HD/4)
        int q = (int)(j & 255);
        int l = (int)(row & (LSEQ - 1));
        int n = (int)(row >> 12);
        int c = l / CHK;
        float4 P = pa4[j];
        float4 V = pb4[j];
        float4 I = pi4[(size_t)c * (NB * HD / 4) + (size_t)n * (HD / 4) + q];
        float4 o;
        o.x = __expf(logaddexpf(P.x + I.x, V.x));
        o.y = __expf(logaddexpf(P.y + I.y, V.y));
        o.z = __expf(logaddexpf(P.z + I.z, V.z));
        o.w = __expf(logaddexpf(P.w + I.w, V.w));
        out4[j] = o;
    }
}

extern "C" void kernel_launch(void* const* d_in, const int* in_sizes, int n_in,
                              void* d_out, int out_size) {
    const float* x    = (const float*)d_in[0];
    const float* W    = (const float*)d_in[1];
    const float* bias = (const float*)d_in[2];
    const float* hx   = (const float*)d_in[3];
    float* out = (float*)d_out;

    cudaFuncSetAttribute(gemm_kernel,
                         cudaFuncAttributeMaxDynamicSharedMemorySize, SMEM_BYTES);

    cvt_kernel<<<2048, 256>>>(x, W);
    dim3 grid(HD / BNR, MTOT / BM);   // (8, 256)
    gemm_kernel<<<grid, NTHR, SMEM_BYTES>>>(bias);

    scan_p1_kernel<<<(NB * HD * NCH) / 256, 256>>>();
    scan_p2_kernel<<<(NB * HD) / 256, 256>>>(hx);
    scan_p3_kernel<<<4096, 256>>>(out);
}

// round 8
// speedup vs baseline: 5.6253x; 1.1453x over previous
#include <cuda_runtime.h>
#include <cuda_fp16.h>
#include <math.h>
#include <float.h>
#include <stdint.h>

#define NB    8
#define LSEQ  4096
#define HIN   1024
#define HD    1024
#define MTOT  (NB * LSEQ)        // 32768

#define BM    128
#define BNC   256
#define BNR   128
#define BK    64
#define STAGES 3
#define KIT   (HIN / BK)         // 16
#define NTHR  512

#define PITCHH 72
#define AHALF  (BM * PITCHH)     // 9216
#define BHALF  (BNC * PITCHH)    // 18432
#define STAGEH (AHALF + BHALF)   // 27648 halves
#define SMEM_BYTES (STAGES * STAGEH * 2)   // 165888
#define EPIPITCH 258
#define SEGSM_OFF (BM * EPIPITCH)          // float offset of seg arrays (132096 B)

#define NCH   32                 // scan chunks (CHK == BM)
#define CHK   (LSEQ / NCH)       // 128

// Static scratch (no runtime allocation allowed)
__device__ __half g_xh[(size_t)MTOT * HIN];
__device__ __half g_wh[(size_t)2 * HD * HIN];
__device__ float  g_a [(size_t)MTOT * HD];     // chunk prefix P_t
__device__ float  g_b [(size_t)MTOT * HD];     // chunk-local scan v_t
__device__ float  g_init[NCH * NB * HD];       // incoming log_h per chunk

__device__ __forceinline__ uint32_t smem_u32(const void* p) {
    uint32_t a;
    asm("{ .reg .u64 t; cvta.to.shared.u64 t, %1; cvt.u32.u64 %0, t; }" : "=r"(a) : "l"(p));
    return a;
}
__device__ __forceinline__ void cp16(uint32_t dst, const void* src) {
    asm volatile("cp.async.cg.shared.global [%0], [%1], 16;" :: "r"(dst), "l"(src) : "memory");
}
__device__ __forceinline__ void ldsm4(uint32_t& r0, uint32_t& r1, uint32_t& r2, uint32_t& r3,
                                      uint32_t addr) {
    asm volatile("ldmatrix.sync.aligned.m8n8.x4.shared.b16 {%0,%1,%2,%3}, [%4];"
                 : "=r"(r0), "=r"(r1), "=r"(r2), "=r"(r3) : "r"(addr));
}
__device__ __forceinline__ float softplusf(float v) {
    return v > 20.f ? v : log1pf(__expf(v));
}
__device__ __forceinline__ float logaddexpf(float u, float v) {
    float mx = fmaxf(u, v), mn = fminf(u, v);
    return mx + __logf(1.f + __expf(mn - mx));
}

// ---------------------------------------------------------------------------
__global__ void __launch_bounds__(256) cvt_kernel(
    const float* __restrict__ x, const float* __restrict__ W)
{
    size_t i = (size_t)blockIdx.x * blockDim.x + threadIdx.x;
    size_t stride = (size_t)gridDim.x * blockDim.x;
    const float4* x4 = (const float4*)x;
    __half2* xo = (__half2*)g_xh;
    size_t nx = (size_t)MTOT * HIN / 4;
    for (size_t j = i; j < nx; j += stride) {
        float4 v = x4[j];
        xo[j * 2 + 0] = __floats2half2_rn(v.x, v.y);
        xo[j * 2 + 1] = __floats2half2_rn(v.z, v.w);
    }
    const float4* w4 = (const float4*)W;
    __half2* wo = (__half2*)g_wh;
    size_t nw = (size_t)2 * HD * HIN / 4;
    for (size_t j = i; j < nw; j += stride) {
        float4 v = w4[j];
        wo[j * 2 + 0] = __floats2half2_rn(v.x, v.y);
        wo[j * 2 + 1] = __floats2half2_rn(v.z, v.w);
    }
}

// ---------------------------------------------------------------------------
// fp16 mma.sync GEMM + fused activation + fused chunk-local scan (phase 1)
// ---------------------------------------------------------------------------
__global__ void __launch_bounds__(NTHR, 1) gemm_kernel(const float* __restrict__ bias)
{
    extern __shared__ __half smh[];
    float* smf = (float*)smh;
    const int tid  = threadIdx.x;
    const int wid  = tid >> 5;
    const int lane = tid & 31;
    const int g    = lane >> 2;
    const int c    = lane & 3;
    const int m0   = blockIdx.y * BM;
    const int h0   = blockIdx.x * BNR;
    const uint32_t sbase = smem_u32(smh);

    const __half* gA[2]; uint32_t dA[2];
#pragma unroll
    for (int i = 0; i < 2; i++) {
        int ci = tid + i * NTHR;
        int row = ci >> 3, ch = ci & 7;
        gA[i] = g_xh + (size_t)(m0 + row) * HIN + ch * 8;
        dA[i] = (uint32_t)(row * 144 + ch * 16);
    }
    const __half* gB[4]; uint32_t dB[4];
#pragma unroll
    for (int i = 0; i < 4; i++) {
        int ci = tid + i * NTHR;
        int row = ci >> 3, ch = ci & 7;
        int wrow = (row < 128) ? (h0 + row) : (HD + h0 + row - 128);
        gB[i] = g_wh + (size_t)wrow * HIN + ch * 8;
        dB[i] = (uint32_t)(AHALF * 2 + row * 144 + ch * 16);
    }

#define ISSUE(KT) do {                                                        \
    int _kt = (KT);                                                           \
    if (_kt < KIT) {                                                          \
        uint32_t _s = sbase + (uint32_t)(_kt % STAGES) * (STAGEH * 2);        \
        _Pragma("unroll")                                                     \
        for (int _i = 0; _i < 2; _i++) cp16(_s + dA[_i], gA[_i] + _kt * BK);  \
        _Pragma("unroll")                                                     \
        for (int _i = 0; _i < 4; _i++) cp16(_s + dB[_i], gB[_i] + _kt * BK);  \
    }                                                                         \
    asm volatile("cp.async.commit_group;" ::: "memory");                      \
} while (0)

    ISSUE(0);
    ISSUE(1);

    const int mw = (wid >> 2) * 32;
    const int nw = (wid & 3) * 64;

    const int aj = lane >> 3;
    const int arow = mw + (aj & 1) * 8 + (lane & 7);
    const uint32_t aoff = (uint32_t)(arow * 144 + (aj >> 1) * 16);
    const int bj = lane >> 3;
    const int brow_base = nw + (bj >> 1) * 8 + (lane & 7);
    const uint32_t bkoff = (uint32_t)((bj & 1) * 16);

    float d[2][8][4];
#pragma unroll
    for (int mt = 0; mt < 2; mt++)
#pragma unroll
        for (int nt = 0; nt < 8; nt++)
#pragma unroll
            for (int q = 0; q < 4; q++) d[mt][nt][q] = 0.f;

    for (int kt = 0; kt < KIT; kt++) {
        asm volatile("cp.async.wait_group 1;" ::: "memory");
        __syncthreads();
        ISSUE(kt + 2);

        const uint32_t sa = sbase + (uint32_t)(kt % STAGES) * (STAGEH * 2);
        const uint32_t sb = sa + AHALF * 2;

#pragma unroll
        for (int s16 = 0; s16 < 4; s16++) {
            const uint32_t kbyte = (uint32_t)(s16 * 32);
            uint32_t af[2][4], bf[8][2];
#pragma unroll
            for (int mt = 0; mt < 2; mt++)
                ldsm4(af[mt][0], af[mt][1], af[mt][2], af[mt][3],
                      sa + aoff + (uint32_t)(mt * 16 * 144) + kbyte);
#pragma unroll
            for (int p = 0; p < 4; p++) {
                int ntp = p * 2;
                ldsm4(bf[ntp][0], bf[ntp][1], bf[ntp+1][0], bf[ntp+1][1],
                      sb + (uint32_t)((brow_base + ntp * 8) * 144) + bkoff + kbyte);
            }
#pragma unroll
            for (int mt = 0; mt < 2; mt++)
#pragma unroll
                for (int nt = 0; nt < 8; nt++) {
                    asm volatile(
                        "mma.sync.aligned.m16n8k16.row.col.f32.f16.f16.f32 "
                        "{%0,%1,%2,%3}, {%4,%5,%6,%7}, {%8,%9}, {%0,%1,%2,%3};"
                        : "+f"(d[mt][nt][0]), "+f"(d[mt][nt][1]),
                          "+f"(d[mt][nt][2]), "+f"(d[mt][nt][3])
                        : "r"(af[mt][0]), "r"(af[mt][1]), "r"(af[mt][2]), "r"(af[mt][3]),
                          "r"(bf[nt][0]), "r"(bf[nt][1]));
                }
        }
    }
    __syncthreads();

    // ---- epilogue step 1: acc -> smem tile (z | h_inter), pitch 258
#pragma unroll
    for (int mt = 0; mt < 2; mt++)
#pragma unroll
        for (int nt = 0; nt < 8; nt++) {
            int r   = mw + mt * 16 + g;
            int col = nw + nt * 8 + 2 * c;
            *(float2*)&smf[r * EPIPITCH + col]       = make_float2(d[mt][nt][0], d[mt][nt][1]);
            *(float2*)&smf[(r + 8) * EPIPITCH + col] = make_float2(d[mt][nt][2], d[mt][nt][3]);
        }
    __syncthreads();

    // ---- step 2: activations in place (z slot <- A=log_c, hi slot <- B=log_z+ltH)
#pragma unroll 4
    for (int it = 0; it < 32; it++) {
        int flat = it * NTHR + tid;
        int m  = flat >> 7;
        int ch = flat & 127;
        float z  = smf[m * EPIPITCH + ch]       + __ldg(bias + h0 + ch);
        float hi = smf[m * EPIPITCH + 128 + ch] + __ldg(bias + HD + h0 + ch);
        float log_z = -softplusf(-z);
        float log_c = -softplusf(z);
        float ltH   = (hi >= 0.f) ? __logf(hi + 0.5f) : -softplusf(-hi);
        smf[m * EPIPITCH + ch]       = log_c;
        smf[m * EPIPITCH + 128 + ch] = log_z + ltH;
    }
    __syncthreads();

    // ---- step 3: segmented chunk-local scan, pass 1 (4 segs x 32 rows per ch)
    // this CTA's 128 rows are exactly one scan chunk (fixed n, l-chunk)
    const int sch = tid & 127;          // channel 0..127
    const int seg = tid >> 7;           // segment 0..3
    float* sPend = smf + SEGSM_OFF;             // [4][128]
    float* sVend = smf + SEGSM_OFF + 4 * 128;   // [4][128]
    {
        float P = 0.f, v = -FLT_MAX;
#pragma unroll 4
        for (int l = seg * 32; l < seg * 32 + 32; l++) {
            float A = smf[l * EPIPITCH + sch];
            float B = smf[l * EPIPITCH + 128 + sch];
            P += A;
            v = logaddexpf(A + v, B);
            smf[l * EPIPITCH + sch]       = P;   // segment-local prefix
            smf[l * EPIPITCH + 128 + sch] = v;   // segment-local value
        }
        sPend[seg * 128 + sch] = P;
        sVend[seg * 128 + sch] = v;
    }
    __syncthreads();

    // ---- step 4: combine 4 segment summaries -> incoming (Pbase, V) per seg
    if (tid < 128) {
        float Pb = 0.f, V = -FLT_MAX;
#pragma unroll
        for (int s = 0; s < 4; s++) {
            float Pe = sPend[s * 128 + tid];
            float Ve = sVend[s * 128 + tid];
            sPend[s * 128 + tid] = Pb;           // overwrite with incoming
            sVend[s * 128 + tid] = V;
            V  = logaddexpf(Pe + V, Ve);
            Pb += Pe;
        }
    }
    __syncthreads();

    // ---- step 5: apply incoming state, write final (P, v) to global
    {
        float Pb = sPend[seg * 128 + sch];
        float V  = sVend[seg * 128 + sch];
#pragma unroll 4
        for (int l = seg * 32; l < seg * 32 + 32; l++) {
            float Pl = smf[l * EPIPITCH + sch];
            float vl = smf[l * EPIPITCH + 128 + sch];
            size_t idx = (size_t)(m0 + l) * HD + h0 + sch;
            g_a[idx] = Pb + Pl;
            g_b[idx] = logaddexpf(Pl + V, vl);
        }
    }
}

// ---------------------------------------------------------------------------
// Scan phase 2: serial composition over NCH chunk summaries per (n,h)
// ---------------------------------------------------------------------------
__global__ void __launch_bounds__(256) scan_p2_kernel(const float* __restrict__ hx)
{
    int t = blockIdx.x * blockDim.x + threadIdx.x;   // 0..NB*HD-1
    if (t >= NB * HD) return;
    int n = t >> 10;
    int h = t & (HD - 1);

    float logh = __logf(hx[t]);
#pragma unroll
    for (int c = 0; c < NCH; c++) {
        g_init[c * (NB * HD) + t] = logh;
        size_t eidx = ((size_t)n * LSEQ + (size_t)c * CHK + (CHK - 1)) * HD + h;
        logh = logaddexpf(g_a[eidx] + logh, g_b[eidx]);
    }
}

// ---------------------------------------------------------------------------
// Scan phase 3: out = exp(logaddexp(P + init, v)), fully parallel, float4
// ---------------------------------------------------------------------------
__global__ void __launch_bounds__(256) scan_p3_kernel(float* __restrict__ out)
{
    size_t i = (size_t)blockIdx.x * blockDim.x + threadIdx.x;
    size_t stride = (size_t)gridDim.x * blockDim.x;
    const float4* pa4 = (const float4*)g_a;
    const float4* pb4 = (const float4*)g_b;
    const float4* pi4 = (const float4*)g_init;
    float4* out4 = (float4*)out;
    size_t total = (size_t)MTOT * HD / 4;

    for (size_t j = i; j < total; j += stride) {
        size_t row = j >> 8;
        int q = (int)(j & 255);
        int l = (int)(row & (LSEQ - 1));
        int n = (int)(row >> 12);
        int c = l / CHK;
        float4 P = pa4[j];
        float4 V = pb4[j];
        float4 I = pi4[(size_t)c * (NB * HD / 4) + (size_t)n * (HD / 4) + q];
        float4 o;
        o.x = __expf(logaddexpf(P.x + I.x, V.x));
        o.y = __expf(logaddexpf(P.y + I.y, V.y));
        o.z = __expf(logaddexpf(P.z + I.z, V.z));
        o.w = __expf(logaddexpf(P.w + I.w, V.w));
        out4[j] = o;
    }
}

extern "C" void kernel_launch(void* const* d_in, const int* in_sizes, int n_in,
                              void* d_out, int out_size) {
    const float* x    = (const float*)d_in[0];
    const float* W    = (const float*)d_in[1];
    const float* bias = (const float*)d_in[2];
    const float* hx   = (const float*)d_in[3];
    float* out = (float*)d_out;

    cudaFuncSetAttribute(gemm_kernel,
                         cudaFuncAttributeMaxDynamicSharedMemorySize, SMEM_BYTES);

    cvt_kernel<<<2048, 256>>>(x, W);
    dim3 grid(HD / BNR, MTOT / BM);   // (8, 256)
    gemm_kernel<<<grid, NTHR, SMEM_BYTES>>>(bias);

    scan_p2_kernel<<<(NB * HD) / 256, 256>>>(hx);
    scan_p3_kernel<<<4096, 256>>>(out);
}

// round 9
// speedup vs baseline: 5.8683x; 1.0432x over previous
#include <cuda_runtime.h>
#include <cuda_fp16.h>
#include <math.h>
#include <float.h>
#include <stdint.h>

#define NB    8
#define LSEQ  4096
#define HIN   1024
#define HD    1024
#define MTOT  (NB * LSEQ)        // 32768

#define BM    128
#define BNC   256
#define BNR   128
#define BK    64
#define STAGES 3
#define KIT   (HIN / BK)         // 16
#define NTHR  512

#define PITCHH 72
#define AHALF  (BM * PITCHH)     // 9216
#define BHALF  (BNC * PITCHH)    // 18432
#define STAGEH (AHALF + BHALF)   // 27648 halves
#define SMEM_BYTES (STAGES * STAGEH * 2)   // 165888
#define EPIPITCH 258
#define SEGSM_OFF (BM * EPIPITCH)

#define NCH   32                 // scan chunks (CHK == BM)
#define CHK   (LSEQ / NCH)       // 128

// Static scratch (no runtime allocation allowed)
__device__ __half g_xh[(size_t)MTOT * HIN];
__device__ __half g_wh[(size_t)2 * HD * HIN];
__device__ float  g_a [(size_t)MTOT * HD];     // chunk prefix P_t
__device__ float  g_b [(size_t)MTOT * HD];     // chunk-local scan v_t
__device__ float  g_init[NCH * NB * HD];       // incoming log_h per chunk
__device__ float  g_Pend[(size_t)NB * HD * NCH];  // chunk endpoint P, [t][c]
__device__ float  g_Vend[(size_t)NB * HD * NCH];  // chunk endpoint V, [t][c]

__device__ __forceinline__ uint32_t smem_u32(const void* p) {
    uint32_t a;
    asm("{ .reg .u64 t; cvta.to.shared.u64 t, %1; cvt.u32.u64 %0, t; }" : "=r"(a) : "l"(p));
    return a;
}
__device__ __forceinline__ void cp16(uint32_t dst, const void* src) {
    asm volatile("cp.async.cg.shared.global [%0], [%1], 16;" :: "r"(dst), "l"(src) : "memory");
}
__device__ __forceinline__ void ldsm4(uint32_t& r0, uint32_t& r1, uint32_t& r2, uint32_t& r3,
                                      uint32_t addr) {
    asm volatile("ldmatrix.sync.aligned.m8n8.x4.shared.b16 {%0,%1,%2,%3}, [%4];"
                 : "=r"(r0), "=r"(r1), "=r"(r2), "=r"(r3) : "r"(addr));
}
__device__ __forceinline__ float softplusf(float v) {
    return v > 20.f ? v : log1pf(__expf(v));
}
__device__ __forceinline__ float logaddexpf(float u, float v) {
    float mx = fmaxf(u, v), mn = fminf(u, v);
    return mx + __logf(1.f + __expf(mn - mx));
}

// ---------------------------------------------------------------------------
__global__ void __launch_bounds__(256) cvt_kernel(
    const float* __restrict__ x, const float* __restrict__ W)
{
    size_t i = (size_t)blockIdx.x * blockDim.x + threadIdx.x;
    size_t stride = (size_t)gridDim.x * blockDim.x;
    const float4* x4 = (const float4*)x;
    __half2* xo = (__half2*)g_xh;
    size_t nx = (size_t)MTOT * HIN / 4;
    for (size_t j = i; j < nx; j += stride) {
        float4 v = x4[j];
        xo[j * 2 + 0] = __floats2half2_rn(v.x, v.y);
        xo[j * 2 + 1] = __floats2half2_rn(v.z, v.w);
    }
    const float4* w4 = (const float4*)W;
    __half2* wo = (__half2*)g_wh;
    size_t nw = (size_t)2 * HD * HIN / 4;
    for (size_t j = i; j < nw; j += stride) {
        float4 v = w4[j];
        wo[j * 2 + 0] = __floats2half2_rn(v.x, v.y);
        wo[j * 2 + 1] = __floats2half2_rn(v.z, v.w);
    }
}

// ---------------------------------------------------------------------------
// fp16 mma.sync GEMM + fused activation + fused chunk-local scan (phase 1)
// ---------------------------------------------------------------------------
__global__ void __launch_bounds__(NTHR, 1) gemm_kernel(const float* __restrict__ bias)
{
    extern __shared__ __half smh[];
    float* smf = (float*)smh;
    const int tid  = threadIdx.x;
    const int wid  = tid >> 5;
    const int lane = tid & 31;
    const int g    = lane >> 2;
    const int c    = lane & 3;
    const int m0   = blockIdx.y * BM;
    const int h0   = blockIdx.x * BNR;
    const uint32_t sbase = smem_u32(smh);

    const __half* gA[2]; uint32_t dA[2];
#pragma unroll
    for (int i = 0; i < 2; i++) {
        int ci = tid + i * NTHR;
        int row = ci >> 3, ch = ci & 7;
        gA[i] = g_xh + (size_t)(m0 + row) * HIN + ch * 8;
        dA[i] = (uint32_t)(row * 144 + ch * 16);
    }
    const __half* gB[4]; uint32_t dB[4];
#pragma unroll
    for (int i = 0; i < 4; i++) {
        int ci = tid + i * NTHR;
        int row = ci >> 3, ch = ci & 7;
        int wrow = (row < 128) ? (h0 + row) : (HD + h0 + row - 128);
        gB[i] = g_wh + (size_t)wrow * HIN + ch * 8;
        dB[i] = (uint32_t)(AHALF * 2 + row * 144 + ch * 16);
    }

#define ISSUE(KT) do {                                                        \
    int _kt = (KT);                                                           \
    if (_kt < KIT) {                                                          \
        uint32_t _s = sbase + (uint32_t)(_kt % STAGES) * (STAGEH * 2);        \
        _Pragma("unroll")                                                     \
        for (int _i = 0; _i < 2; _i++) cp16(_s + dA[_i], gA[_i] + _kt * BK);  \
        _Pragma("unroll")                                                     \
        for (int _i = 0; _i < 4; _i++) cp16(_s + dB[_i], gB[_i] + _kt * BK);  \
    }                                                                         \
    asm volatile("cp.async.commit_group;" ::: "memory");                      \
} while (0)

    ISSUE(0);
    ISSUE(1);

    const int mw = (wid >> 2) * 32;
    const int nw = (wid & 3) * 64;

    const int aj = lane >> 3;
    const int arow = mw + (aj & 1) * 8 + (lane & 7);
    const uint32_t aoff = (uint32_t)(arow * 144 + (aj >> 1) * 16);
    const int bj = lane >> 3;
    const int brow_base = nw + (bj >> 1) * 8 + (lane & 7);
    const uint32_t bkoff = (uint32_t)((bj & 1) * 16);

    float d[2][8][4];
#pragma unroll
    for (int mt = 0; mt < 2; mt++)
#pragma unroll
        for (int nt = 0; nt < 8; nt++)
#pragma unroll
            for (int q = 0; q < 4; q++) d[mt][nt][q] = 0.f;

    for (int kt = 0; kt < KIT; kt++) {
        asm volatile("cp.async.wait_group 1;" ::: "memory");
        __syncthreads();
        ISSUE(kt + 2);

        const uint32_t sa = sbase + (uint32_t)(kt % STAGES) * (STAGEH * 2);
        const uint32_t sb = sa + AHALF * 2;

        // A fragments double-buffered across s16
        uint32_t afc[2][4], afn[2][4];
#pragma unroll
        for (int mt = 0; mt < 2; mt++)
            ldsm4(afc[mt][0], afc[mt][1], afc[mt][2], afc[mt][3],
                  sa + aoff + (uint32_t)(mt * 16 * 144));

#pragma unroll
        for (int s16 = 0; s16 < 4; s16++) {
            const uint32_t kbyte = (uint32_t)(s16 * 32);
            if (s16 < 3) {
#pragma unroll
                for (int mt = 0; mt < 2; mt++)
                    ldsm4(afn[mt][0], afn[mt][1], afn[mt][2], afn[mt][3],
                          sa + aoff + (uint32_t)(mt * 16 * 144) + kbyte + 32);
            }
            uint32_t bf[8][2];
#pragma unroll
            for (int p = 0; p < 4; p++) {
                int ntp = p * 2;
                ldsm4(bf[ntp][0], bf[ntp][1], bf[ntp+1][0], bf[ntp+1][1],
                      sb + (uint32_t)((brow_base + ntp * 8) * 144) + bkoff + kbyte);
            }
#pragma unroll
            for (int mt = 0; mt < 2; mt++)
#pragma unroll
                for (int nt = 0; nt < 8; nt++) {
                    asm volatile(
                        "mma.sync.aligned.m16n8k16.row.col.f32.f16.f16.f32 "
                        "{%0,%1,%2,%3}, {%4,%5,%6,%7}, {%8,%9}, {%0,%1,%2,%3};"
                        : "+f"(d[mt][nt][0]), "+f"(d[mt][nt][1]),
                          "+f"(d[mt][nt][2]), "+f"(d[mt][nt][3])
                        : "r"(afc[mt][0]), "r"(afc[mt][1]), "r"(afc[mt][2]), "r"(afc[mt][3]),
                          "r"(bf[nt][0]), "r"(bf[nt][1]));
                }
#pragma unroll
            for (int mt = 0; mt < 2; mt++)
#pragma unroll
                for (int q = 0; q < 4; q++) afc[mt][q] = afn[mt][q];
        }
    }
    __syncthreads();

    // ---- epilogue step 1: acc -> smem tile (z | h_inter), pitch 258
#pragma unroll
    for (int mt = 0; mt < 2; mt++)
#pragma unroll
        for (int nt = 0; nt < 8; nt++) {
            int r   = mw + mt * 16 + g;
            int col = nw + nt * 8 + 2 * c;
            *(float2*)&smf[r * EPIPITCH + col]       = make_float2(d[mt][nt][0], d[mt][nt][1]);
            *(float2*)&smf[(r + 8) * EPIPITCH + col] = make_float2(d[mt][nt][2], d[mt][nt][3]);
        }
    __syncthreads();

    // ---- step 2: fused activation + segmented chunk-local scan (pass 1)
    const int sch = tid & 127;          // channel 0..127
    const int seg = tid >> 7;           // segment 0..3
    float* sPend = smf + SEGSM_OFF;             // [4][128]
    float* sVend = smf + SEGSM_OFF + 4 * 128;   // [4][128]
    const float bz = __ldg(bias + h0 + sch);
    const float bh = __ldg(bias + HD + h0 + sch);
    {
        float P = 0.f, v = -FLT_MAX;
#pragma unroll 4
        for (int l = seg * 32; l < seg * 32 + 32; l++) {
            float z  = smf[l * EPIPITCH + sch]       + bz;
            float hi = smf[l * EPIPITCH + 128 + sch] + bh;
            float A   = -softplusf(z);                               // log(1-sig)
            float ltH = (hi >= 0.f) ? __logf(hi + 0.5f) : -softplusf(-hi);
            float B   = -softplusf(-z) + ltH;                        // log sig + log g
            P += A;
            v = logaddexpf(A + v, B);
            smf[l * EPIPITCH + sch]       = P;   // segment-local prefix
            smf[l * EPIPITCH + 128 + sch] = v;   // segment-local value
        }
        sPend[seg * 128 + sch] = P;
        sVend[seg * 128 + sch] = v;
    }
    __syncthreads();

    // ---- step 3: combine 4 segment summaries -> incoming (Pbase, V) per seg
    if (tid < 128) {
        float Pb = 0.f, V = -FLT_MAX;
#pragma unroll
        for (int s = 0; s < 4; s++) {
            float Pe = sPend[s * 128 + tid];
            float Ve = sVend[s * 128 + tid];
            sPend[s * 128 + tid] = Pb;
            sVend[s * 128 + tid] = V;
            V  = logaddexpf(Pe + V, Ve);
            Pb += Pe;
        }
    }
    __syncthreads();

    // ---- step 4: apply incoming state, write final (P, v) + chunk endpoints
    {
        float Pb = sPend[seg * 128 + sch];
        float V  = sVend[seg * 128 + sch];
        float Pf = 0.f, vf = -FLT_MAX;
#pragma unroll 4
        for (int l = seg * 32; l < seg * 32 + 32; l++) {
            float Pl = smf[l * EPIPITCH + sch];
            float vl = smf[l * EPIPITCH + 128 + sch];
            Pf = Pb + Pl;
            vf = logaddexpf(Pl + V, vl);
            size_t idx = (size_t)(m0 + l) * HD + h0 + sch;
            g_a[idx] = Pf;
            g_b[idx] = vf;
        }
        if (seg == 3) {
            int n = m0 >> 12;
            int cch = (m0 & (LSEQ - 1)) >> 7;
            size_t eidx = ((size_t)n * HD + h0 + sch) * NCH + cch;
            g_Pend[eidx] = Pf;
            g_Vend[eidx] = vf;
        }
    }
}

// ---------------------------------------------------------------------------
// Scan phase 2: one warp per (n,h); Kogge-Stone shuffle scan over 32 chunks.
// Operator: (P1,V1) then (P2,V2) -> (P1+P2, logaddexp(P2+V1, V2))
// ---------------------------------------------------------------------------
__global__ void __launch_bounds__(256) scan_p2_kernel(const float* __restrict__ hx)
{
    int w = (blockIdx.x * blockDim.x + threadIdx.x) >> 5;   // 0..NB*HD-1
    int lane = threadIdx.x & 31;
    if (w >= NB * HD) return;

    float P = g_Pend[(size_t)w * NCH + lane];
    float V = g_Vend[(size_t)w * NCH + lane];

    // inclusive scan
#pragma unroll
    for (int dlt = 1; dlt < 32; dlt <<= 1) {
        float Pp = __shfl_up_sync(0xFFFFFFFF, P, dlt);
        float Vp = __shfl_up_sync(0xFFFFFFFF, V, dlt);
        if (lane >= dlt) {
            V = logaddexpf(P + Vp, V);
            P = P + Pp;
        }
    }
    // exclusive
    float Pe = __shfl_up_sync(0xFFFFFFFF, P, 1);
    float Ve = __shfl_up_sync(0xFFFFFFFF, V, 1);
    if (lane == 0) { Pe = 0.f; Ve = -FLT_MAX; }

    float logh0 = __logf(hx[w]);
    g_init[lane * (NB * HD) + w] = logaddexpf(Pe + logh0, Ve);
}

// ---------------------------------------------------------------------------
// Scan phase 3: out = exp(logaddexp(P + init, v)), fully parallel, float4
// ---------------------------------------------------------------------------
__global__ void __launch_bounds__(256) scan_p3_kernel(float* __restrict__ out)
{
    size_t i = (size_t)blockIdx.x * blockDim.x + threadIdx.x;
    size_t stride = (size_t)gridDim.x * blockDim.x;
    const float4* pa4 = (const float4*)g_a;
    const float4* pb4 = (const float4*)g_b;
    const float4* pi4 = (const float4*)g_init;
    float4* out4 = (float4*)out;
    size_t total = (size_t)MTOT * HD / 4;

    for (size_t j = i; j < total; j += stride) {
        size_t row = j >> 8;
        int q = (int)(j & 255);
        int l = (int)(row & (LSEQ - 1));
        int n = (int)(row >> 12);
        int c = l / CHK;
        float4 P = pa4[j];
        float4 V = pb4[j];
        float4 I = pi4[(size_t)c * (NB * HD / 4) + (size_t)n * (HD / 4) + q];
        float4 o;
        o.x = __expf(logaddexpf(P.x + I.x, V.x));
        o.y = __expf(logaddexpf(P.y + I.y, V.y));
        o.z = __expf(logaddexpf(P.z + I.z, V.z));
        o.w = __expf(logaddexpf(P.w + I.w, V.w));
        out4[j] = o;
    }
}

extern "C" void kernel_launch(void* const* d_in, const int* in_sizes, int n_in,
                              void* d_out, int out_size) {
    const float* x    = (const float*)d_in[0];
    const float* W    = (const float*)d_in[1];
    const float* bias = (const float*)d_in[2];
    const float* hx   = (const float*)d_in[3];
    float* out = (float*)d_out;

    cudaFuncSetAttribute(gemm_kernel,
                         cudaFuncAttributeMaxDynamicSharedMemorySize, SMEM_BYTES);

    cvt_kernel<<<2048, 256>>>(x, W);
    dim3 grid(HD / BNR, MTOT / BM);   // (8, 256)
    gemm_kernel<<<grid, NTHR, SMEM_BYTES>>>(bias);

    scan_p2_kernel<<<(NB * HD * 32) / 256, 256>>>(hx);
    scan_p3_kernel<<<4096, 256>>>(out);
}

// round 10
// speedup vs baseline: 7.1140x; 1.2123x over previous
#include <cuda_runtime.h>
#include <cuda_fp16.h>
#include <math.h>
#include <float.h>
#include <stdint.h>

#define NB    8
#define LSEQ  4096
#define HIN   1024
#define HD    1024
#define MTOT  (NB * LSEQ)        // 32768

#define BM    128
#define BNC   256
#define BNR   128
#define BK    64
#define STAGES 3
#define KIT   (HIN / BK)         // 16
#define NTHR  512

#define PITCHH 72
#define AHALF  (BM * PITCHH)     // 9216
#define BHALF  (BNC * PITCHH)    // 18432
#define STAGEH (AHALF + BHALF)   // 27648 halves
#define SMEM_BYTES (STAGES * STAGEH * 2)   // 165888
#define EPIPITCH 258
#define SEGSM_OFF (BM * EPIPITCH)

#define NCH   32                 // scan chunks (CHK == BM)
#define CHK   (LSEQ / NCH)       // 128
#define TCH   (NB * HD)          // 8192 channels

// Static scratch (no runtime allocation allowed)
__device__ __half g_xh[(size_t)MTOT * HIN];
__device__ __half g_wh[(size_t)2 * HD * HIN];
__device__ float  g_a [(size_t)MTOT * HD];        // segment-local prefix Pl
__device__ float  g_b [(size_t)MTOT * HD];        // segment-local value  vl
__device__ float  g_init[NCH * TCH];              // incoming log_h per chunk [c][t]
__device__ float  g_Pend[(size_t)TCH * NCH];      // chunk endpoint P, [t][c]
__device__ float  g_Vend[(size_t)TCH * NCH];      // chunk endpoint V, [t][c]
__device__ float  g_segP[(size_t)NCH * 4 * TCH];  // per-seg incoming P, [c][s][n][h]
__device__ float  g_segV[(size_t)NCH * 4 * TCH];  // per-seg incoming V, [c][s][n][h]

__device__ __forceinline__ uint32_t smem_u32(const void* p) {
    uint32_t a;
    asm("{ .reg .u64 t; cvta.to.shared.u64 t, %1; cvt.u32.u64 %0, t; }" : "=r"(a) : "l"(p));
    return a;
}
__device__ __forceinline__ void cp16(uint32_t dst, const void* src) {
    asm volatile("cp.async.cg.shared.global [%0], [%1], 16;" :: "r"(dst), "l"(src) : "memory");
}
__device__ __forceinline__ void ldsm4(uint32_t& r0, uint32_t& r1, uint32_t& r2, uint32_t& r3,
                                      uint32_t addr) {
    asm volatile("ldmatrix.sync.aligned.m8n8.x4.shared.b16 {%0,%1,%2,%3}, [%4];"
                 : "=r"(r0), "=r"(r1), "=r"(r2), "=r"(r3) : "r"(addr));
}
__device__ __forceinline__ float logaddexpf(float u, float v) {
    float mx = fmaxf(u, v), mn = fminf(u, v);
    return mx + __logf(1.f + __expf(mn - mx));
}

// ---------------------------------------------------------------------------
__global__ void __launch_bounds__(256) cvt_kernel(
    const float* __restrict__ x, const float* __restrict__ W)
{
    size_t i = (size_t)blockIdx.x * blockDim.x + threadIdx.x;
    size_t stride = (size_t)gridDim.x * blockDim.x;
    const float4* x4 = (const float4*)x;
    __half2* xo = (__half2*)g_xh;
    size_t nx = (size_t)MTOT * HIN / 4;
    for (size_t j = i; j < nx; j += stride) {
        float4 v = x4[j];
        xo[j * 2 + 0] = __floats2half2_rn(v.x, v.y);
        xo[j * 2 + 1] = __floats2half2_rn(v.z, v.w);
    }
    const float4* w4 = (const float4*)W;
    __half2* wo = (__half2*)g_wh;
    size_t nw = (size_t)2 * HD * HIN / 4;
    for (size_t j = i; j < nw; j += stride) {
        float4 v = w4[j];
        wo[j * 2 + 0] = __floats2half2_rn(v.x, v.y);
        wo[j * 2 + 1] = __floats2half2_rn(v.z, v.w);
    }
}

// ---------------------------------------------------------------------------
// fp16 mma.sync GEMM + fused activation + segment-local scan
// ---------------------------------------------------------------------------
__global__ void __launch_bounds__(NTHR, 1) gemm_kernel(const float* __restrict__ bias)
{
    extern __shared__ __half smh[];
    float* smf = (float*)smh;
    const int tid  = threadIdx.x;
    const int wid  = tid >> 5;
    const int lane = tid & 31;
    const int g    = lane >> 2;
    const int c    = lane & 3;
    const int m0   = blockIdx.y * BM;
    const int h0   = blockIdx.x * BNR;
    const uint32_t sbase = smem_u32(smh);

    const __half* gA[2]; uint32_t dA[2];
#pragma unroll
    for (int i = 0; i < 2; i++) {
        int ci = tid + i * NTHR;
        int row = ci >> 3, ch = ci & 7;
        gA[i] = g_xh + (size_t)(m0 + row) * HIN + ch * 8;
        dA[i] = (uint32_t)(row * 144 + ch * 16);
    }
    const __half* gB[4]; uint32_t dB[4];
#pragma unroll
    for (int i = 0; i < 4; i++) {
        int ci = tid + i * NTHR;
        int row = ci >> 3, ch = ci & 7;
        int wrow = (row < 128) ? (h0 + row) : (HD + h0 + row - 128);
        gB[i] = g_wh + (size_t)wrow * HIN + ch * 8;
        dB[i] = (uint32_t)(AHALF * 2 + row * 144 + ch * 16);
    }

#define ISSUE(KT) do {                                                        \
    int _kt = (KT);                                                           \
    if (_kt < KIT) {                                                          \
        uint32_t _s = sbase + (uint32_t)(_kt % STAGES) * (STAGEH * 2);        \
        _Pragma("unroll")                                                     \
        for (int _i = 0; _i < 2; _i++) cp16(_s + dA[_i], gA[_i] + _kt * BK);  \
        _Pragma("unroll")                                                     \
        for (int _i = 0; _i < 4; _i++) cp16(_s + dB[_i], gB[_i] + _kt * BK);  \
    }                                                                         \
    asm volatile("cp.async.commit_group;" ::: "memory");                      \
} while (0)

    ISSUE(0);
    ISSUE(1);

    const int mw = (wid >> 2) * 32;
    const int nw = (wid & 3) * 64;

    const int aj = lane >> 3;
    const int arow = mw + (aj & 1) * 8 + (lane & 7);
    const uint32_t aoff = (uint32_t)(arow * 144 + (aj >> 1) * 16);
    const int bj = lane >> 3;
    const int brow_base = nw + (bj >> 1) * 8 + (lane & 7);
    const uint32_t bkoff = (uint32_t)((bj & 1) * 16);

    float d[2][8][4];
#pragma unroll
    for (int mt = 0; mt < 2; mt++)
#pragma unroll
        for (int nt = 0; nt < 8; nt++)
#pragma unroll
            for (int q = 0; q < 4; q++) d[mt][nt][q] = 0.f;

    for (int kt = 0; kt < KIT; kt++) {
        asm volatile("cp.async.wait_group 1;" ::: "memory");
        __syncthreads();
        ISSUE(kt + 2);

        const uint32_t sa = sbase + (uint32_t)(kt % STAGES) * (STAGEH * 2);
        const uint32_t sb = sa + AHALF * 2;

        uint32_t afc[2][4], afn[2][4];
#pragma unroll
        for (int mt = 0; mt < 2; mt++)
            ldsm4(afc[mt][0], afc[mt][1], afc[mt][2], afc[mt][3],
                  sa + aoff + (uint32_t)(mt * 16 * 144));

#pragma unroll
        for (int s16 = 0; s16 < 4; s16++) {
            const uint32_t kbyte = (uint32_t)(s16 * 32);
            if (s16 < 3) {
#pragma unroll
                for (int mt = 0; mt < 2; mt++)
                    ldsm4(afn[mt][0], afn[mt][1], afn[mt][2], afn[mt][3],
                          sa + aoff + (uint32_t)(mt * 16 * 144) + kbyte + 32);
            }
            uint32_t bf[8][2];
#pragma unroll
            for (int p = 0; p < 4; p++) {
                int ntp = p * 2;
                ldsm4(bf[ntp][0], bf[ntp][1], bf[ntp+1][0], bf[ntp+1][1],
                      sb + (uint32_t)((brow_base + ntp * 8) * 144) + bkoff + kbyte);
            }
#pragma unroll
            for (int mt = 0; mt < 2; mt++)
#pragma unroll
                for (int nt = 0; nt < 8; nt++) {
                    asm volatile(
                        "mma.sync.aligned.m16n8k16.row.col.f32.f16.f16.f32 "
                        "{%0,%1,%2,%3}, {%4,%5,%6,%7}, {%8,%9}, {%0,%1,%2,%3};"
                        : "+f"(d[mt][nt][0]), "+f"(d[mt][nt][1]),
                          "+f"(d[mt][nt][2]), "+f"(d[mt][nt][3])
                        : "r"(afc[mt][0]), "r"(afc[mt][1]), "r"(afc[mt][2]), "r"(afc[mt][3]),
                          "r"(bf[nt][0]), "r"(bf[nt][1]));
                }
#pragma unroll
            for (int mt = 0; mt < 2; mt++)
#pragma unroll
                for (int q = 0; q < 4; q++) afc[mt][q] = afn[mt][q];
        }
    }
    __syncthreads();

    // ---- step 1: acc -> smem tile (z | h_inter), pitch 258
#pragma unroll
    for (int mt = 0; mt < 2; mt++)
#pragma unroll
        for (int nt = 0; nt < 8; nt++) {
            int r   = mw + mt * 16 + g;
            int col = nw + nt * 8 + 2 * c;
            *(float2*)&smf[r * EPIPITCH + col]       = make_float2(d[mt][nt][0], d[mt][nt][1]);
            *(float2*)&smf[(r + 8) * EPIPITCH + col] = make_float2(d[mt][nt][2], d[mt][nt][3]);
        }
    __syncthreads();

    // ---- step 2: fused activation + segment-local scan; write Pl,vl direct
    const int sch = tid & 127;
    const int seg = tid >> 7;
    float* sPend = smf + SEGSM_OFF;             // [4][128]
    float* sVend = smf + SEGSM_OFF + 4 * 128;
    const float bz = __ldg(bias + h0 + sch);
    const float bh = __ldg(bias + HD + h0 + sch);
    {
        float P = 0.f, v = -FLT_MAX;
#pragma unroll 4
        for (int l = seg * 32; l < seg * 32 + 32; l++) {
            float z  = smf[l * EPIPITCH + sch]       + bz;
            float hi = smf[l * EPIPITCH + 128 + sch] + bh;
            // s = softplus(-z); log(1-sig) = -(z+s); log sig = -s
            float s  = fmaxf(-z, 0.f) + __logf(1.f + __expf(-fabsf(z)));
            float A  = -(z + s);
            float ltH = (hi >= 0.f) ? __logf(hi + 0.5f)
                                    : hi - __logf(1.f + __expf(hi));
            float B  = ltH - s;
            P += A;
            v = logaddexpf(A + v, B);
            size_t idx = (size_t)(m0 + l) * HD + h0 + sch;
            g_a[idx] = P;       // segment-local prefix
            g_b[idx] = v;       // segment-local value
        }
        sPend[seg * 128 + sch] = P;
        sVend[seg * 128 + sch] = v;
    }
    __syncthreads();

    // ---- step 3: combine seg summaries -> per-seg incoming + chunk endpoint
    if (tid < 128) {
        int n   = m0 >> 12;
        int cch = (m0 & (LSEQ - 1)) >> 7;
        float Pb = 0.f, V = -FLT_MAX;
#pragma unroll
        for (int s = 0; s < 4; s++) {
            float Pe = sPend[s * 128 + tid];
            float Ve = sVend[s * 128 + tid];
            size_t sidx = ((size_t)(cch * 4 + s) * NB + n) * HD + h0 + tid;
            g_segP[sidx] = Pb;
            g_segV[sidx] = V;
            V  = logaddexpf(Pe + V, Ve);
            Pb += Pe;
        }
        size_t eidx = ((size_t)n * HD + h0 + tid) * NCH + cch;
        g_Pend[eidx] = Pb;
        g_Vend[eidx] = V;
    }
}

// ---------------------------------------------------------------------------
// Scan phase 2: one warp per (n,h); Kogge-Stone scan over 32 chunk states
// ---------------------------------------------------------------------------
__global__ void __launch_bounds__(256) scan_p2_kernel(const float* __restrict__ hx)
{
    int w = (blockIdx.x * blockDim.x + threadIdx.x) >> 5;
    int lane = threadIdx.x & 31;
    if (w >= TCH) return;

    float P = g_Pend[(size_t)w * NCH + lane];
    float V = g_Vend[(size_t)w * NCH + lane];

#pragma unroll
    for (int dlt = 1; dlt < 32; dlt <<= 1) {
        float Pp = __shfl_up_sync(0xFFFFFFFF, P, dlt);
        float Vp = __shfl_up_sync(0xFFFFFFFF, V, dlt);
        if (lane >= dlt) {
            V = logaddexpf(P + Vp, V);
            P = P + Pp;
        }
    }
    float Pe = __shfl_up_sync(0xFFFFFFFF, P, 1);
    float Ve = __shfl_up_sync(0xFFFFFFFF, V, 1);
    if (lane == 0) { Pe = 0.f; Ve = -FLT_MAX; }

    float logh0 = __logf(hx[w]);
    g_init[lane * TCH + w] = logaddexpf(Pe + logh0, Ve);
}

// ---------------------------------------------------------------------------
// Scan phase 3: J = logaddexp(Pb+I, V); out = exp(logaddexp(Pl + J, vl))
// ---------------------------------------------------------------------------
__global__ void __launch_bounds__(256) scan_p3_kernel(float* __restrict__ out)
{
    size_t i = (size_t)blockIdx.x * blockDim.x + threadIdx.x;
    size_t stride = (size_t)gridDim.x * blockDim.x;
    const float4* pa4 = (const float4*)g_a;
    const float4* pb4 = (const float4*)g_b;
    const float4* pi4 = (const float4*)g_init;
    const float4* sp4 = (const float4*)g_segP;
    const float4* sv4 = (const float4*)g_segV;
    float4* out4 = (float4*)out;
    size_t total = (size_t)MTOT * HD / 4;

    for (size_t j = i; j < total; j += stride) {
        size_t row = j >> 8;
        int q = (int)(j & 255);
        int l = (int)(row & (LSEQ - 1));
        int n = (int)(row >> 12);
        int c = l >> 7;
        int s = (l >> 5) & 3;
        size_t tq = (size_t)n * (HD / 4) + q;
        float4 Pl = pa4[j];
        float4 vl = pb4[j];
        float4 I  = pi4[(size_t)c * (TCH / 4) + tq];
        float4 Pb = sp4[(size_t)(c * 4 + s) * (TCH / 4) + tq];
        float4 V  = sv4[(size_t)(c * 4 + s) * (TCH / 4) + tq];
        float4 o;
        o.x = __expf(logaddexpf(Pl.x + logaddexpf(Pb.x + I.x, V.x), vl.x));
        o.y = __expf(logaddexpf(Pl.y + logaddexpf(Pb.y + I.y, V.y), vl.y));
        o.z = __expf(logaddexpf(Pl.z + logaddexpf(Pb.z + I.z, V.z), vl.z));
        o.w = __expf(logaddexpf(Pl.w + logaddexpf(Pb.w + I.w, V.w), vl.w));
        out4[j] = o;
    }
}

extern "C" void kernel_launch(void* const* d_in, const int* in_sizes, int n_in,
                              void* d_out, int out_size) {
    const float* x    = (const float*)d_in[0];
    const float* W    = (const float*)d_in[1];
    const float* bias = (const float*)d_in[2];
    const float* hx   = (const float*)d_in[3];
    float* out = (float*)d_out;

    cudaFuncSetAttribute(gemm_kernel,
                         cudaFuncAttributeMaxDynamicSharedMemorySize, SMEM_BYTES);

    cvt_kernel<<<2048, 256>>>(x, W);
    dim3 grid(HD / BNR, MTOT / BM);   // (8, 256)
    gemm_kernel<<<grid, NTHR, SMEM_BYTES>>>(bias);

    scan_p2_kernel<<<(TCH * 32) / 256, 256>>>(hx);
    scan_p3_kernel<<<4096, 256>>>(out);
}

// round 11
// speedup vs baseline: 7.9733x; 1.1208x over previous
#include <cuda_runtime.h>
#include <cuda_fp16.h>
#include <math.h>
#include <float.h>
#include <stdint.h>

#define NB    8
#define LSEQ  4096
#define HIN   1024
#define HD    1024
#define MTOT  (NB * LSEQ)        // 32768

#define BM    128
#define BNC   128                // combined N per CTA (64 z + 64 h_inter)
#define BNR   64                 // real channels per CTA
#define BK    64
#define STAGES 2
#define KIT   (HIN / BK)         // 16
#define NTHR  256

#define PITCHH 72                // halves per row (144 B)
#define AHALF  (BM * PITCHH)     // 9216
#define BHALF  (BNC * PITCHH)    // 9216
#define STAGEH (AHALF + BHALF)   // 18432 halves = 36864 B
#define SMEM_BYTES (STAGES * STAGEH * 2)   // 73728
#define EPIPITCH 132
#define SEGSM_OFF (BM * EPIPITCH)          // 16896 floats

#define NCH   32                 // scan chunks (CHK == BM)
#define CHK   (LSEQ / NCH)       // 128
#define TCH   (NB * HD)          // 8192 channels

// Static scratch (no runtime allocation allowed)
__device__ __half g_xh[(size_t)MTOT * HIN];
__device__ __half g_wh[(size_t)2 * HD * HIN];
__device__ float  g_a [(size_t)MTOT * HD];        // segment-local prefix Pl
__device__ float  g_b [(size_t)MTOT * HD];        // segment-local value  vl
__device__ float  g_init[NCH * TCH];              // incoming log_h per chunk [c][t]
__device__ float  g_Pend[(size_t)TCH * NCH];      // chunk endpoint P, [t][c]
__device__ float  g_Vend[(size_t)TCH * NCH];      // chunk endpoint V, [t][c]
__device__ float  g_segP[(size_t)NCH * 4 * TCH];  // per-seg incoming P, [c][s][n][h]
__device__ float  g_segV[(size_t)NCH * 4 * TCH];  // per-seg incoming V, [c][s][n][h]

__device__ __forceinline__ uint32_t smem_u32(const void* p) {
    uint32_t a;
    asm("{ .reg .u64 t; cvta.to.shared.u64 t, %1; cvt.u32.u64 %0, t; }" : "=r"(a) : "l"(p));
    return a;
}
__device__ __forceinline__ void cp16(uint32_t dst, const void* src) {
    asm volatile("cp.async.cg.shared.global [%0], [%1], 16;" :: "r"(dst), "l"(src) : "memory");
}
__device__ __forceinline__ void ldsm4(uint32_t& r0, uint32_t& r1, uint32_t& r2, uint32_t& r3,
                                      uint32_t addr) {
    asm volatile("ldmatrix.sync.aligned.m8n8.x4.shared.b16 {%0,%1,%2,%3}, [%4];"
                 : "=r"(r0), "=r"(r1), "=r"(r2), "=r"(r3) : "r"(addr));
}
__device__ __forceinline__ float logaddexpf(float u, float v) {
    float mx = fmaxf(u, v), mn = fminf(u, v);
    return mx + __logf(1.f + __expf(mn - mx));
}

// ---------------------------------------------------------------------------
__global__ void __launch_bounds__(256) cvt_kernel(
    const float* __restrict__ x, const float* __restrict__ W)
{
    size_t i = (size_t)blockIdx.x * blockDim.x + threadIdx.x;
    size_t stride = (size_t)gridDim.x * blockDim.x;
    const float4* x4 = (const float4*)x;
    __half2* xo = (__half2*)g_xh;
    size_t nx = (size_t)MTOT * HIN / 4;
    for (size_t j = i; j < nx; j += stride) {
        float4 v = x4[j];
        xo[j * 2 + 0] = __floats2half2_rn(v.x, v.y);
        xo[j * 2 + 1] = __floats2half2_rn(v.z, v.w);
    }
    const float4* w4 = (const float4*)W;
    __half2* wo = (__half2*)g_wh;
    size_t nw = (size_t)2 * HD * HIN / 4;
    for (size_t j = i; j < nw; j += stride) {
        float4 v = w4[j];
        wo[j * 2 + 0] = __floats2half2_rn(v.x, v.y);
        wo[j * 2 + 1] = __floats2half2_rn(v.z, v.w);
    }
}

// ---------------------------------------------------------------------------
// fp16 mma.sync GEMM (2 CTAs/SM ping-pong) + fused activation + segment scan
// ---------------------------------------------------------------------------
__global__ void __launch_bounds__(NTHR, 2) gemm_kernel(const float* __restrict__ bias)
{
    extern __shared__ __half smh[];
    float* smf = (float*)smh;
    const int tid  = threadIdx.x;
    const int wid  = tid >> 5;
    const int lane = tid & 31;
    const int g    = lane >> 2;
    const int c    = lane & 3;
    const int m0   = blockIdx.y * BM;
    const int h0   = blockIdx.x * BNR;
    const uint32_t sbase = smem_u32(smh);

    // cp.async chunk descriptors (16B = 8 halves): A 4/thread, B 4/thread
    const __half* gA[4]; uint32_t dA[4];
#pragma unroll
    for (int i = 0; i < 4; i++) {
        int ci = tid + i * NTHR;          // 0..1023
        int row = ci >> 3, ch = ci & 7;
        gA[i] = g_xh + (size_t)(m0 + row) * HIN + ch * 8;
        dA[i] = (uint32_t)(row * 144 + ch * 16);
    }
    const __half* gB[4]; uint32_t dB[4];
#pragma unroll
    for (int i = 0; i < 4; i++) {
        int ci = tid + i * NTHR;          // 0..1023
        int row = ci >> 3, ch = ci & 7;
        int wrow = (row < 64) ? (h0 + row) : (HD + h0 + row - 64);
        gB[i] = g_wh + (size_t)wrow * HIN + ch * 8;
        dB[i] = (uint32_t)(AHALF * 2 + row * 144 + ch * 16);
    }

#define ISSUE(KT) do {                                                        \
    int _kt = (KT);                                                           \
    if (_kt < KIT) {                                                          \
        uint32_t _s = sbase + (uint32_t)(_kt % STAGES) * (STAGEH * 2);        \
        _Pragma("unroll")                                                     \
        for (int _i = 0; _i < 4; _i++) cp16(_s + dA[_i], gA[_i] + _kt * BK);  \
        _Pragma("unroll")                                                     \
        for (int _i = 0; _i < 4; _i++) cp16(_s + dB[_i], gB[_i] + _kt * BK);  \
    }                                                                         \
    asm volatile("cp.async.commit_group;" ::: "memory");                      \
} while (0)

    ISSUE(0);

    // 8 warps: 4(M) x 2(Ncomb); warp tile 32 x 64 -> 2 Mtiles x 8 Ntiles
    const int mw = (wid >> 1) * 32;
    const int nw = (wid & 1) * 64;

    const int aj = lane >> 3;
    const int arow = mw + (aj & 1) * 8 + (lane & 7);
    const uint32_t aoff = (uint32_t)(arow * 144 + (aj >> 1) * 16);
    const int bj = lane >> 3;
    const int brow_base = nw + (bj >> 1) * 8 + (lane & 7);
    const uint32_t bkoff = (uint32_t)((bj & 1) * 16);

    float d[2][8][4];
#pragma unroll
    for (int mt = 0; mt < 2; mt++)
#pragma unroll
        for (int nt = 0; nt < 8; nt++)
#pragma unroll
            for (int q = 0; q < 4; q++) d[mt][nt][q] = 0.f;

    for (int kt = 0; kt < KIT; kt++) {
        ISSUE(kt + 1);
        asm volatile("cp.async.wait_group 1;" ::: "memory");
        __syncthreads();

        const uint32_t sa = sbase + (uint32_t)(kt % STAGES) * (STAGEH * 2);
        const uint32_t sb = sa + AHALF * 2;

        uint32_t afc[2][4], afn[2][4];
#pragma unroll
        for (int mt = 0; mt < 2; mt++)
            ldsm4(afc[mt][0], afc[mt][1], afc[mt][2], afc[mt][3],
                  sa + aoff + (uint32_t)(mt * 16 * 144));

#pragma unroll
        for (int s16 = 0; s16 < 4; s16++) {
            const uint32_t kbyte = (uint32_t)(s16 * 32);
            if (s16 < 3) {
#pragma unroll
                for (int mt = 0; mt < 2; mt++)
                    ldsm4(afn[mt][0], afn[mt][1], afn[mt][2], afn[mt][3],
                          sa + aoff + (uint32_t)(mt * 16 * 144) + kbyte + 32);
            }
            uint32_t bf[8][2];
#pragma unroll
            for (int p = 0; p < 4; p++) {
                int ntp = p * 2;
                ldsm4(bf[ntp][0], bf[ntp][1], bf[ntp+1][0], bf[ntp+1][1],
                      sb + (uint32_t)((brow_base + ntp * 8) * 144) + bkoff + kbyte);
            }
#pragma unroll
            for (int mt = 0; mt < 2; mt++)
#pragma unroll
                for (int nt = 0; nt < 8; nt++) {
                    asm volatile(
                        "mma.sync.aligned.m16n8k16.row.col.f32.f16.f16.f32 "
                        "{%0,%1,%2,%3}, {%4,%5,%6,%7}, {%8,%9}, {%0,%1,%2,%3};"
                        : "+f"(d[mt][nt][0]), "+f"(d[mt][nt][1]),
                          "+f"(d[mt][nt][2]), "+f"(d[mt][nt][3])
                        : "r"(afc[mt][0]), "r"(afc[mt][1]), "r"(afc[mt][2]), "r"(afc[mt][3]),
                          "r"(bf[nt][0]), "r"(bf[nt][1]));
                }
#pragma unroll
            for (int mt = 0; mt < 2; mt++)
#pragma unroll
                for (int q = 0; q < 4; q++) afc[mt][q] = afn[mt][q];
        }
        __syncthreads();   // protect stage kt%2 before ISSUE(kt+2) overwrites
    }

    // ---- step 1: acc -> smem tile (z | h_inter), pitch 132
#pragma unroll
    for (int mt = 0; mt < 2; mt++)
#pragma unroll
        for (int nt = 0; nt < 8; nt++) {
            int r   = mw + mt * 16 + g;
            int col = nw + nt * 8 + 2 * c;
            *(float2*)&smf[r * EPIPITCH + col]       = make_float2(d[mt][nt][0], d[mt][nt][1]);
            *(float2*)&smf[(r + 8) * EPIPITCH + col] = make_float2(d[mt][nt][2], d[mt][nt][3]);
        }
    __syncthreads();

    // ---- step 2: fused activation + segment-local scan; write Pl,vl direct
    const int sch = tid & 63;           // channel 0..63
    const int seg = tid >> 6;           // segment 0..3
    float* sPend = smf + SEGSM_OFF;             // [4][64]
    float* sVend = smf + SEGSM_OFF + 4 * 64;
    const float bz = __ldg(bias + h0 + sch);
    const float bh = __ldg(bias + HD + h0 + sch);
    {
        float P = 0.f, v = -FLT_MAX;
#pragma unroll 4
        for (int l = seg * 32; l < seg * 32 + 32; l++) {
            float z  = smf[l * EPIPITCH + sch]      + bz;
            float hi = smf[l * EPIPITCH + 64 + sch] + bh;
            float s  = fmaxf(-z, 0.f) + __logf(1.f + __expf(-fabsf(z)));
            float A  = -(z + s);
            float ltH = (hi >= 0.f) ? __logf(hi + 0.5f)
                                    : hi - __logf(1.f + __expf(hi));
            float B  = ltH - s;
            P += A;
            v = logaddexpf(A + v, B);
            size_t idx = (size_t)(m0 + l) * HD + h0 + sch;
            g_a[idx] = P;
            g_b[idx] = v;
        }
        sPend[seg * 64 + sch] = P;
        sVend[seg * 64 + sch] = v;
    }
    __syncthreads();

    // ---- step 3: combine seg summaries -> per-seg incoming + chunk endpoint
    if (tid < 64) {
        int n   = m0 >> 12;
        int cch = (m0 & (LSEQ - 1)) >> 7;
        float Pb = 0.f, V = -FLT_MAX;
#pragma unroll
        for (int s = 0; s < 4; s++) {
            float Pe = sPend[s * 64 + tid];
            float Ve = sVend[s * 64 + tid];
            size_t sidx = ((size_t)(cch * 4 + s) * NB + n) * HD + h0 + tid;
            g_segP[sidx] = Pb;
            g_segV[sidx] = V;
            V  = logaddexpf(Pe + V, Ve);
            Pb += Pe;
        }
        size_t eidx = ((size_t)n * HD + h0 + tid) * NCH + cch;
        g_Pend[eidx] = Pb;
        g_Vend[eidx] = V;
    }
}

// ---------------------------------------------------------------------------
// Scan phase 2: one warp per (n,h); Kogge-Stone scan over 32 chunk states
// ---------------------------------------------------------------------------
__global__ void __launch_bounds__(256) scan_p2_kernel(const float* __restrict__ hx)
{
    int w = (blockIdx.x * blockDim.x + threadIdx.x) >> 5;
    int lane = threadIdx.x & 31;
    if (w >= TCH) return;

    float P = g_Pend[(size_t)w * NCH + lane];
    float V = g_Vend[(size_t)w * NCH + lane];

#pragma unroll
    for (int dlt = 1; dlt < 32; dlt <<= 1) {
        float Pp = __shfl_up_sync(0xFFFFFFFF, P, dlt);
        float Vp = __shfl_up_sync(0xFFFFFFFF, V, dlt);
        if (lane >= dlt) {
            V = logaddexpf(P + Vp, V);
            P = P + Pp;
        }
    }
    float Pe = __shfl_up_sync(0xFFFFFFFF, P, 1);
    float Ve = __shfl_up_sync(0xFFFFFFFF, V, 1);
    if (lane == 0) { Pe = 0.f; Ve = -FLT_MAX; }

    float logh0 = __logf(hx[w]);
    g_init[lane * TCH + w] = logaddexpf(Pe + logh0, Ve);
}

// ---------------------------------------------------------------------------
// Scan phase 3: J = logaddexp(Pb+I, V); out = exp(logaddexp(Pl + J, vl))
// ---------------------------------------------------------------------------
__global__ void __launch_bounds__(256) scan_p3_kernel(float* __restrict__ out)
{
    size_t i = (size_t)blockIdx.x * blockDim.x + threadIdx.x;
    size_t stride = (size_t)gridDim.x * blockDim.x;
    const float4* pa4 = (const float4*)g_a;
    const float4* pb4 = (const float4*)g_b;
    const float4* pi4 = (const float4*)g_init;
    const float4* sp4 = (const float4*)g_segP;
    const float4* sv4 = (const float4*)g_segV;
    float4* out4 = (float4*)out;
    size_t total = (size_t)MTOT * HD / 4;

    for (size_t j = i; j < total; j += stride) {
        size_t row = j >> 8;
        int q = (int)(j & 255);
        int l = (int)(row & (LSEQ - 1));
        int n = (int)(row >> 12);
        int c = l >> 7;
        int s = (l >> 5) & 3;
        size_t tq = (size_t)n * (HD / 4) + q;
        float4 Pl = pa4[j];
        float4 vl = pb4[j];
        float4 I  = pi4[(size_t)c * (TCH / 4) + tq];
        float4 Pb = sp4[(size_t)(c * 4 + s) * (TCH / 4) + tq];
        float4 V  = sv4[(size_t)(c * 4 + s) * (TCH / 4) + tq];
        float4 o;
        o.x = __expf(logaddexpf(Pl.x + logaddexpf(Pb.x + I.x, V.x), vl.x));
        o.y = __expf(logaddexpf(Pl.y + logaddexpf(Pb.y + I.y, V.y), vl.y));
        o.z = __expf(logaddexpf(Pl.z + logaddexpf(Pb.z + I.z, V.z), vl.z));
        o.w = __expf(logaddexpf(Pl.w + logaddexpf(Pb.w + I.w, V.w), vl.w));
        out4[j] = o;
    }
}

extern "C" void kernel_launch(void* const* d_in, const int* in_sizes, int n_in,
                              void* d_out, int out_size) {
    const float* x    = (const float*)d_in[0];
    const float* W    = (const float*)d_in[1];
    const float* bias = (const float*)d_in[2];
    const float* hx   = (const float*)d_in[3];
    float* out = (float*)d_out;

    cudaFuncSetAttribute(gemm_kernel,
                         cudaFuncAttributeMaxDynamicSharedMemorySize, SMEM_BYTES);

    cvt_kernel<<<2048, 256>>>(x, W);
    dim3 grid(HD / BNR, MTOT / BM);   // (16, 256)
    gemm_kernel<<<grid, NTHR, SMEM_BYTES>>>(bias);

    scan_p2_kernel<<<(TCH * 32) / 256, 256>>>(hx);
    scan_p3_kernel<<<4096, 256>>>(out);
}